// round 1
// baseline (speedup 1.0000x reference)
#include <cuda_runtime.h>
#include <math.h>

#define NB  2
#define NS  2048
#define ND  1024
#define NH  16
#define NDH 64

// Scratch (allocation-free rule: __device__ globals). Head-major [B,H,S,DH].
__device__ float g_Q [NB*NH*NS*NDH];
__device__ float g_K [NB*NH*NS*NDH];
__device__ float g_V [NB*NH*NS*NDH];
__device__ float g_AO[NB*NH*NS*NDH];

// ---------------------------------------------------------------------------
// Fused Q/K/V projection: 128x128x16 SGEMM, 8x8 per thread, 256 threads.
// Writes directly into head-major layout for the attention kernel.
// ---------------------------------------------------------------------------
__global__ __launch_bounds__(256) void qkv_proj_kernel(
    const float* __restrict__ Xq, const float* __restrict__ Xk, const float* __restrict__ Xv,
    const float* __restrict__ Wq, const float* __restrict__ Wk, const float* __restrict__ Wv)
{
    __shared__ float As[16][132];   // As[k][m], padded
    __shared__ float Bs[16][132];   // Bs[k][n], padded

    const float *X, *W; float *Out;
    if (blockIdx.z == 0)      { X = Xq; W = Wq; Out = g_Q; }
    else if (blockIdx.z == 1) { X = Xk; W = Wk; Out = g_K; }
    else                      { X = Xv; W = Wv; Out = g_V; }

    const int tid = threadIdx.x;
    const int tx  = tid & 15, ty = tid >> 4;
    const int bM  = blockIdx.y * 128, bN = blockIdx.x * 128;

    float acc[8][8];
    #pragma unroll
    for (int i = 0; i < 8; i++)
        #pragma unroll
        for (int j = 0; j < 8; j++) acc[i][j] = 0.f;

    for (int k0 = 0; k0 < ND; k0 += 16) {
        #pragma unroll
        for (int l = 0; l < 2; l++) {
            int f  = tid + l * 256;
            int r  = f >> 2, c4 = f & 3;
            float4 v = *(const float4*)(X + (size_t)(bM + r) * ND + k0 + c4 * 4);
            As[c4*4+0][r] = v.x; As[c4*4+1][r] = v.y;
            As[c4*4+2][r] = v.z; As[c4*4+3][r] = v.w;
            int rb = f >> 5, cb = f & 31;
            *(float4*)&Bs[rb][cb*4] =
                *(const float4*)(W + (size_t)(k0 + rb) * ND + bN + cb * 4);
        }
        __syncthreads();
        #pragma unroll
        for (int k = 0; k < 16; k++) {
            float a[8], b[8];
            *(float4*)&a[0] = *(float4*)&As[k][ty*4];
            *(float4*)&a[4] = *(float4*)&As[k][64 + ty*4];
            *(float4*)&b[0] = *(float4*)&Bs[k][tx*4];
            *(float4*)&b[4] = *(float4*)&Bs[k][64 + tx*4];
            #pragma unroll
            for (int i = 0; i < 8; i++)
                #pragma unroll
                for (int j = 0; j < 8; j++) acc[i][j] += a[i] * b[j];
        }
        __syncthreads();
    }

    // Epilogue: scatter into [B,H,S,DH]
    #pragma unroll
    for (int rh = 0; rh < 2; rh++)
        #pragma unroll
        for (int i = 0; i < 4; i++) {
            int m  = bM + rh * 64 + ty * 4 + i;
            int bb = m >> 11, s = m & 2047;
            #pragma unroll
            for (int ch = 0; ch < 2; ch++) {
                int n0 = bN + ch * 64 + tx * 4;
                int h  = n0 >> 6, dh = n0 & 63;
                float4 v = make_float4(acc[rh*4+i][ch*4+0], acc[rh*4+i][ch*4+1],
                                       acc[rh*4+i][ch*4+2], acc[rh*4+i][ch*4+3]);
                *(float4*)(Out + (((size_t)(bb * NH + h) * NS + s) * NDH + dh)) = v;
            }
        }
}

// ---------------------------------------------------------------------------
// Flash attention, fp32. One CTA = 64 queries of one (b,h). 64-wide K blocks.
// Skips K blocks entirely beyond valid_len (exactly equivalent: exp(-1e6-m)
// underflows to 0 in fp32 in the reference softmax).
// Smem: Qt[64][64] (d-major), KtP[64][68] (K tile, reused for P tile), Vs[64][64].
// ---------------------------------------------------------------------------
#define ATTN_SMEM_FLOATS (64*64 + 64*68 + 64*64)

__global__ __launch_bounds__(256) void attn_kernel(const int* __restrict__ valid_lens)
{
    extern __shared__ float sm[];
    float (*Qt) [64] = (float(*)[64]) sm;
    float (*KtP)[68] = (float(*)[68])(sm + 64*64);
    float (*Vs) [64] = (float(*)[64])(sm + 64*64 + 64*68);

    const int tid = threadIdx.x;
    const int tx  = tid & 15, ty = tid >> 4;
    const int qb  = blockIdx.x;
    const int bh  = blockIdx.y;
    const int bb  = bh >> 4;             // bh / NH
    const int vlen = valid_lens[bb];
    const int nkb  = (vlen + 63) >> 6;

    const float* Qp = g_Q  + (size_t)bh * NS * NDH;
    const float* Kp = g_K  + (size_t)bh * NS * NDH;
    const float* Vp = g_V  + (size_t)bh * NS * NDH;
    float*       Op = g_AO + (size_t)bh * NS * NDH;

    // Load Q block transposed (Qt[d][row]), pre-scaled by 1/sqrt(DH)=0.125
    const float qscale = 0.125f;
    #pragma unroll
    for (int l = 0; l < 4; l++) {
        int f = tid + l * 256;
        int r = f >> 4, c4 = f & 15;
        float4 v = *(const float4*)(Qp + (size_t)(qb * 64 + r) * NDH + c4 * 4);
        Qt[c4*4+0][r] = v.x * qscale; Qt[c4*4+1][r] = v.y * qscale;
        Qt[c4*4+2][r] = v.z * qscale; Qt[c4*4+3][r] = v.w * qscale;
    }

    float m_i[4], l_i[4], o[4][4];
    #pragma unroll
    for (int i = 0; i < 4; i++) {
        m_i[i] = -1e30f; l_i[i] = 0.f;
        #pragma unroll
        for (int j = 0; j < 4; j++) o[i][j] = 0.f;
    }

    for (int kb = 0; kb < nkb; kb++) {
        __syncthreads();   // prev iter done reading KtP/Vs (and Q visible on iter 0)
        #pragma unroll
        for (int l = 0; l < 4; l++) {
            int f = tid + l * 256;
            int r = f >> 4, c4 = f & 15;
            const float* krow = Kp + (size_t)(kb * 64 + r) * NDH + c4 * 4;
            float4 kv = *(const float4*)krow;
            KtP[c4*4+0][r] = kv.x; KtP[c4*4+1][r] = kv.y;
            KtP[c4*4+2][r] = kv.z; KtP[c4*4+3][r] = kv.w;
            *(float4*)&Vs[r][c4*4] =
                *(const float4*)(Vp + (size_t)(kb * 64 + r) * NDH + c4 * 4);
        }
        __syncthreads();

        // S = (Q*scale) @ K^T ; thread owns rows ty*4..+3, cols tx*4..+3
        float sc[4][4];
        #pragma unroll
        for (int i = 0; i < 4; i++)
            #pragma unroll
            for (int j = 0; j < 4; j++) sc[i][j] = 0.f;
        #pragma unroll 16
        for (int d = 0; d < 64; d++) {
            float4 a  = *(float4*)&Qt[d][ty*4];
            float4 bk = *(float4*)&KtP[d][tx*4];
            sc[0][0] += a.x*bk.x; sc[0][1] += a.x*bk.y; sc[0][2] += a.x*bk.z; sc[0][3] += a.x*bk.w;
            sc[1][0] += a.y*bk.x; sc[1][1] += a.y*bk.y; sc[1][2] += a.y*bk.z; sc[1][3] += a.y*bk.w;
            sc[2][0] += a.z*bk.x; sc[2][1] += a.z*bk.y; sc[2][2] += a.z*bk.z; sc[2][3] += a.z*bk.w;
            sc[3][0] += a.w*bk.x; sc[3][1] += a.w*bk.y; sc[3][2] += a.w*bk.z; sc[3][3] += a.w*bk.w;
        }

        // Mask tail columns of the last block
        int cbase = kb * 64 + tx * 4;
        if (cbase + 3 >= vlen) {
            #pragma unroll
            for (int j = 0; j < 4; j++)
                if (cbase + j >= vlen) {
                    #pragma unroll
                    for (int i = 0; i < 4; i++) sc[i][j] = -1e30f;
                }
        }

        // Online softmax (row groups = 16 lanes within a half-warp)
        #pragma unroll
        for (int i = 0; i < 4; i++) {
            float mx = fmaxf(fmaxf(sc[i][0], sc[i][1]), fmaxf(sc[i][2], sc[i][3]));
            #pragma unroll
            for (int off = 8; off > 0; off >>= 1)
                mx = fmaxf(mx, __shfl_xor_sync(0xffffffffu, mx, off));
            float mnew  = fmaxf(m_i[i], mx);
            float alpha = __expf(m_i[i] - mnew);
            m_i[i] = mnew;
            float s = 0.f;
            #pragma unroll
            for (int j = 0; j < 4; j++) {
                float p = __expf(sc[i][j] - mnew);
                sc[i][j] = p; s += p;
            }
            #pragma unroll
            for (int off = 8; off > 0; off >>= 1)
                s += __shfl_xor_sync(0xffffffffu, s, off);
            l_i[i] = l_i[i] * alpha + s;
            #pragma unroll
            for (int j = 0; j < 4; j++) o[i][j] *= alpha;
        }

        __syncthreads();   // all threads done with K tile
        // P tile into KtP, transposed: Pt[col][row]
        #pragma unroll
        for (int j = 0; j < 4; j++)
            #pragma unroll
            for (int i = 0; i < 4; i++)
                KtP[tx*4 + j][ty*4 + i] = sc[i][j];
        __syncthreads();

        // O += P @ V ; thread owns rows ty*4..+3, d-cols tx*4..+3
        #pragma unroll 16
        for (int j = 0; j < 64; j++) {
            float4 p  = *(float4*)&KtP[j][ty*4];
            float4 vv = *(float4*)&Vs[j][tx*4];
            o[0][0] += p.x*vv.x; o[0][1] += p.x*vv.y; o[0][2] += p.x*vv.z; o[0][3] += p.x*vv.w;
            o[1][0] += p.y*vv.x; o[1][1] += p.y*vv.y; o[1][2] += p.y*vv.z; o[1][3] += p.y*vv.w;
            o[2][0] += p.z*vv.x; o[2][1] += p.z*vv.y; o[2][2] += p.z*vv.z; o[2][3] += p.z*vv.w;
            o[3][0] += p.w*vv.x; o[3][1] += p.w*vv.y; o[3][2] += p.w*vv.z; o[3][3] += p.w*vv.w;
        }
    }

    #pragma unroll
    for (int i = 0; i < 4; i++) {
        float inv = 1.f / l_i[i];
        float4 r = make_float4(o[i][0]*inv, o[i][1]*inv, o[i][2]*inv, o[i][3]*inv);
        *(float4*)(Op + (size_t)(qb * 64 + ty * 4 + i) * NDH + tx * 4) = r;
    }
}

// ---------------------------------------------------------------------------
// Output projection: same SGEMM shape, A gathered from head-major g_AO.
// ---------------------------------------------------------------------------
__global__ __launch_bounds__(256) void out_proj_kernel(
    const float* __restrict__ Wo, float* __restrict__ Out)
{
    __shared__ float As[16][132];
    __shared__ float Bs[16][132];

    const int tid = threadIdx.x;
    const int tx  = tid & 15, ty = tid >> 4;
    const int bM  = blockIdx.y * 128, bN = blockIdx.x * 128;

    float acc[8][8];
    #pragma unroll
    for (int i = 0; i < 8; i++)
        #pragma unroll
        for (int j = 0; j < 8; j++) acc[i][j] = 0.f;

    for (int k0 = 0; k0 < ND; k0 += 16) {
        #pragma unroll
        for (int l = 0; l < 2; l++) {
            int f  = tid + l * 256;
            int r  = f >> 2, c4 = f & 3;
            int m  = bM + r;
            int bb = m >> 11, s = m & 2047;
            int k  = k0 + c4 * 4;
            int h  = k >> 6, dh = k & 63;
            float4 v = *(const float4*)(g_AO + (((size_t)(bb * NH + h) * NS + s) * NDH + dh));
            As[c4*4+0][r] = v.x; As[c4*4+1][r] = v.y;
            As[c4*4+2][r] = v.z; As[c4*4+3][r] = v.w;
            int rb = f >> 5, cb = f & 31;
            *(float4*)&Bs[rb][cb*4] =
                *(const float4*)(Wo + (size_t)(k0 + rb) * ND + bN + cb * 4);
        }
        __syncthreads();
        #pragma unroll
        for (int k = 0; k < 16; k++) {
            float a[8], b[8];
            *(float4*)&a[0] = *(float4*)&As[k][ty*4];
            *(float4*)&a[4] = *(float4*)&As[k][64 + ty*4];
            *(float4*)&b[0] = *(float4*)&Bs[k][tx*4];
            *(float4*)&b[4] = *(float4*)&Bs[k][64 + tx*4];
            #pragma unroll
            for (int i = 0; i < 8; i++)
                #pragma unroll
                for (int j = 0; j < 8; j++) acc[i][j] += a[i] * b[j];
        }
        __syncthreads();
    }

    #pragma unroll
    for (int rh = 0; rh < 2; rh++)
        #pragma unroll
        for (int i = 0; i < 4; i++) {
            int m = bM + rh * 64 + ty * 4 + i;
            #pragma unroll
            for (int ch = 0; ch < 2; ch++) {
                int n0 = bN + ch * 64 + tx * 4;
                float4 v = make_float4(acc[rh*4+i][ch*4+0], acc[rh*4+i][ch*4+1],
                                       acc[rh*4+i][ch*4+2], acc[rh*4+i][ch*4+3]);
                *(float4*)(Out + (size_t)m * ND + n0) = v;
            }
        }
}

// ---------------------------------------------------------------------------
extern "C" void kernel_launch(void* const* d_in, const int* in_sizes, int n_in,
                              void* d_out, int out_size)
{
    const float* q  = (const float*)d_in[0];
    const float* k  = (const float*)d_in[1];
    const float* v  = (const float*)d_in[2];
    const int*   vl = (const int*)  d_in[3];
    const float* Wq = (const float*)d_in[4];
    const float* Wk = (const float*)d_in[5];
    const float* Wv = (const float*)d_in[6];
    const float* Wo = (const float*)d_in[7];
    float* out = (float*)d_out;

    // 50176 B dynamic smem > 48K default: opt in (idempotent, capture-safe).
    cudaFuncSetAttribute(attn_kernel, cudaFuncAttributeMaxDynamicSharedMemorySize,
                         ATTN_SMEM_FLOATS * (int)sizeof(float));

    dim3 gProj(ND / 128, (NB * NS) / 128, 3);
    qkv_proj_kernel<<<gProj, 256>>>(q, k, v, Wq, Wk, Wv);

    dim3 gAttn(NS / 64, NB * NH);
    attn_kernel<<<gAttn, 256, ATTN_SMEM_FLOATS * (int)sizeof(float)>>>(vl);

    dim3 gOut(ND / 128, (NB * NS) / 128);
    out_proj_kernel<<<gOut, 256>>>(Wo, out);
}

// round 3
// speedup vs baseline: 1.5557x; 1.5557x over previous
#include <cuda_runtime.h>
#include <cuda_bf16.h>
#include <stdint.h>

#define NB  2
#define NS  2048
#define ND  1024
#define NH  16
#define NDH 64

// Scratch (allocation-free rule: __device__ globals).
__device__ float g_Q [NB*NH*NS*NDH];          // head-major [B,H,S,DH]
__device__ float g_K [NB*NH*NS*NDH];
__device__ float g_V [NB*NH*NS*NDH];
__device__ float g_AO[NB*NS*ND];              // attention out, [B*S, D] row-major
__device__ __nv_bfloat16 g_Whi[4u << 20];     // 4 x W^T hi: [n][k] k-major
__device__ __nv_bfloat16 g_Wlo[4u << 20];     // 4 x W^T lo

// ---------------------------------------------------------------------------
// helpers
// ---------------------------------------------------------------------------
__device__ __forceinline__ uint32_t smem_u32(const void* p) {
    uint32_t a;
    asm("{ .reg .u64 t; cvta.to.shared.u64 t, %1; cvt.u32.u64 %0, t; }" : "=r"(a) : "l"(p));
    return a;
}
__device__ __forceinline__ void cpasync16(uint32_t dst, const void* src) {
    asm volatile("cp.async.cg.shared.global [%0], [%1], 16;" :: "r"(dst), "l"(src));
}
#define CP_COMMIT() asm volatile("cp.async.commit_group;" ::: "memory")
#define CP_WAIT0()  asm volatile("cp.async.wait_group 0;" ::: "memory")

#define LDSM_X4(r0, r1, r2, r3, addr)                                          \
    asm volatile("ldmatrix.sync.aligned.m8n8.x4.shared.b16 {%0,%1,%2,%3}, [%4];" \
        : "=r"(r0), "=r"(r1), "=r"(r2), "=r"(r3) : "r"(addr))

#define MMA_BF16(d, a, b)                                                      \
    asm volatile("mma.sync.aligned.m16n8k16.row.col.f32.bf16.bf16.f32 "        \
        "{%0,%1,%2,%3},{%4,%5,%6,%7},{%8,%9},{%0,%1,%2,%3};"                   \
        : "+f"((d)[0]), "+f"((d)[1]), "+f"((d)[2]), "+f"((d)[3])               \
        : "r"((a)[0]), "r"((a)[1]), "r"((a)[2]), "r"((a)[3]),                  \
          "r"((b)[0]), "r"((b)[1]))

__device__ __forceinline__ void split2(float a, float b, uint32_t& hi, uint32_t& lo) {
    __nv_bfloat16 ha = __float2bfloat16(a), hb = __float2bfloat16(b);
    float ra = a - __bfloat162float(ha), rb = b - __bfloat162float(hb);
    hi = (uint32_t)__bfloat16_as_ushort(ha) | ((uint32_t)__bfloat16_as_ushort(hb) << 16);
    __nv_bfloat16 la = __float2bfloat16(ra), lb = __float2bfloat16(rb);
    lo = (uint32_t)__bfloat16_as_ushort(la) | ((uint32_t)__bfloat16_as_ushort(lb) << 16);
}

// ---------------------------------------------------------------------------
// W transpose + fp32 -> (bf16 hi, bf16 lo). Out[n][k] = W[k][n].
// ---------------------------------------------------------------------------
__global__ __launch_bounds__(256) void wsplit_kernel(
    const float* __restrict__ W0, const float* __restrict__ W1,
    const float* __restrict__ W2, const float* __restrict__ W3)
{
    __shared__ float t[32][33];
    const float* W = (blockIdx.z == 0) ? W0 : (blockIdx.z == 1) ? W1 :
                     (blockIdx.z == 2) ? W2 : W3;
    __nv_bfloat16* Ohi = g_Whi + ((size_t)blockIdx.z << 20);
    __nv_bfloat16* Olo = g_Wlo + ((size_t)blockIdx.z << 20);

    int tx = threadIdx.x & 31, ty = threadIdx.x >> 5;
    int n0 = blockIdx.x * 32, k0 = blockIdx.y * 32;

    #pragma unroll
    for (int i = 0; i < 4; i++)
        t[ty + i*8][tx] = W[(size_t)(k0 + ty + i*8) * ND + n0 + tx];   // t[k][n]
    __syncthreads();
    #pragma unroll
    for (int i = 0; i < 4; i++) {
        float v = t[tx][ty + i*8];
        __nv_bfloat16 h = __float2bfloat16(v);
        __nv_bfloat16 l = __float2bfloat16(v - __bfloat162float(h));
        size_t idx = (size_t)(n0 + ty + i*8) * ND + k0 + tx;
        Ohi[idx] = h; Olo[idx] = l;
    }
}

// ---------------------------------------------------------------------------
// HMMA split-bf16 GEMM: C[4096,1024] = A[4096,1024] @ W[1024,1024]
// CTA tile 128x128, BK=64, double-buffered, 8 warps (each 32m x 64n).
// D = Ah*Bh + Ah*Bl + Al*Bh.
// Smem per buffer (64 KB): Ahi 16K | Alo 16K | Bhi 16K | Blo 16K; rows = 128B,
// swizzle: byte ^= (row&7)*16.
// ---------------------------------------------------------------------------
#define BUF_BYTES 65536
#define OFS_AHI 0
#define OFS_ALO 16384
#define OFS_BHI 32768
#define OFS_BLO 49152
#define GEMM_SMEM (2 * BUF_BYTES)

__global__ __launch_bounds__(256, 1) void gemm_mma_kernel(
    const float* __restrict__ Xq, const float* __restrict__ Xk,
    const float* __restrict__ Xv, float* __restrict__ Cout, int mode)
{
    extern __shared__ char smc[];
    const uint32_t sb = smem_u32(smc);
    const int tid  = threadIdx.x;
    const int wid  = tid >> 5, lane = tid & 31;
    const int z    = blockIdx.z;

    const float* A;
    const __nv_bfloat16 *Whi, *Wlo;
    float* OutHM = 0;
    if (mode == 0) {
        A = (z == 0) ? Xq : (z == 1) ? Xk : Xv;
        Whi = g_Whi + ((size_t)z << 20);
        Wlo = g_Wlo + ((size_t)z << 20);
        OutHM = (z == 0) ? g_Q : (z == 1) ? g_K : g_V;
    } else {
        A = g_AO;
        Whi = g_Whi + ((size_t)3 << 20);
        Wlo = g_Wlo + ((size_t)3 << 20);
    }
    const int bM = blockIdx.y * 128, bN = blockIdx.x * 128;
    const int warp_m = (wid & 3) * 32, warp_n = (wid >> 2) * 64;

    float acc[16][4];
    #pragma unroll
    for (int i = 0; i < 16; i++)
        #pragma unroll
        for (int j = 0; j < 4; j++) acc[i][j] = 0.f;

    float4 ar[8];

    // ---- stage-load helpers (inlined via lambdas) ----
    auto ldgA = [&](int s) {
        #pragma unroll
        for (int l = 0; l < 8; l++) {
            int f = tid + l * 256;
            ar[l] = *(const float4*)(A + (size_t)(bM + (f >> 4)) * ND + s * 64 + (f & 15) * 4);
        }
    };
    auto stsA = [&](int buf) {
        uint32_t base = sb + buf * BUF_BYTES;
        #pragma unroll
        for (int l = 0; l < 8; l++) {
            int f = tid + l * 256;
            int row = f >> 4, c4 = f & 15;          // c4: float4 index (8 bytes bf16)
            uint2 hi, lo;
            split2(ar[l].x, ar[l].y, hi.x, lo.x);
            split2(ar[l].z, ar[l].w, hi.y, lo.y);
            uint32_t off = row * 128 + ((c4 * 8) ^ ((row & 7) * 16));
            *(uint2*)(smc + (base - sb) + OFS_AHI + off) = hi;
            *(uint2*)(smc + (base - sb) + OFS_ALO + off) = lo;
        }
    };
    auto cpB = [&](int s, int buf) {
        uint32_t base = sb + buf * BUF_BYTES;
        #pragma unroll
        for (int l = 0; l < 8; l++) {
            int f = tid + l * 256;                  // 0..2047
            int arr = f >> 10;                      // 0: hi, 1: lo
            int r   = (f >> 3) & 127;
            int c   = f & 7;                        // 16B chunk
            const __nv_bfloat16* src =
                (arr ? Wlo : Whi) + (size_t)(bN + r) * ND + s * 64 + c * 8;
            uint32_t dst = base + (arr ? OFS_BLO : OFS_BHI)
                         + r * 128 + ((c * 16) ^ ((r & 7) * 16));
            cpasync16(dst, src);
        }
        CP_COMMIT();
    };

    // ---- prologue ----
    ldgA(0);
    stsA(0);
    cpB(0, 0);

    for (int s = 0; s < 16; s++) {
        const int buf = s & 1;
        if (s + 1 < 16) ldgA(s + 1);
        CP_WAIT0();
        __syncthreads();
        if (s + 1 < 16) cpB(s + 1, buf ^ 1);

        const uint32_t aHi = sb + buf * BUF_BYTES + OFS_AHI;
        const uint32_t aLo = sb + buf * BUF_BYTES + OFS_ALO;
        const uint32_t bHi = sb + buf * BUF_BYTES + OFS_BHI;
        const uint32_t bLo = sb + buf * BUF_BYTES + OFS_BLO;

        #pragma unroll
        for (int kk = 0; kk < 4; kk++) {
            const int k0 = kk * 16;
            uint32_t ah[2][4], al[2][4], bh[8][2], bl[8][2];
            // A fragments
            #pragma unroll
            for (int mt = 0; mt < 2; mt++) {
                int row = warp_m + mt * 16 + (lane & 15);
                uint32_t off = row * 128 + ((k0 * 2 + (lane >> 4) * 16) ^ ((row & 7) * 16));
                LDSM_X4(ah[mt][0], ah[mt][1], ah[mt][2], ah[mt][3], aHi + off);
                LDSM_X4(al[mt][0], al[mt][1], al[mt][2], al[mt][3], aLo + off);
            }
            // B fragments (two n-tiles per ldmatrix.x4)
            #pragma unroll
            for (int p = 0; p < 4; p++) {
                int n = warp_n + p * 16 + (lane & 7) + ((lane >> 4) << 3);
                uint32_t off = n * 128 + ((k0 * 2 + ((lane >> 3) & 1) * 16) ^ ((n & 7) * 16));
                LDSM_X4(bh[p*2][0], bh[p*2][1], bh[p*2+1][0], bh[p*2+1][1], bHi + off);
                LDSM_X4(bl[p*2][0], bl[p*2][1], bl[p*2+1][0], bl[p*2+1][1], bLo + off);
            }
            // 48 HMMA
            #pragma unroll
            for (int mt = 0; mt < 2; mt++)
                #pragma unroll
                for (int nt = 0; nt < 8; nt++) {
                    MMA_BF16(acc[mt*8+nt], ah[mt], bh[nt]);
                    MMA_BF16(acc[mt*8+nt], ah[mt], bl[nt]);
                    MMA_BF16(acc[mt*8+nt], al[mt], bh[nt]);
                }
        }
        if (s + 1 < 16) stsA(buf ^ 1);
    }

    // ---- epilogue ----
    #pragma unroll
    for (int mt = 0; mt < 2; mt++)
        #pragma unroll
        for (int nt = 0; nt < 8; nt++) {
            int m0 = bM + warp_m + mt * 16 + (lane >> 2);
            int n  = bN + warp_n + nt * 8 + (lane & 3) * 2;
            float2 v0 = make_float2(acc[mt*8+nt][0], acc[mt*8+nt][1]);
            float2 v1 = make_float2(acc[mt*8+nt][2], acc[mt*8+nt][3]);
            if (mode == 0) {
                int h = n >> 6, dh = n & 63;
                int b0 = m0 >> 11, s0 = m0 & 2047;
                int m1 = m0 + 8, b1 = m1 >> 11, s1 = m1 & 2047;
                *(float2*)(OutHM + (((size_t)(b0 * NH + h) * NS + s0) * NDH + dh)) = v0;
                *(float2*)(OutHM + (((size_t)(b1 * NH + h) * NS + s1) * NDH + dh)) = v1;
            } else {
                *(float2*)(Cout + (size_t)m0 * ND + n)       = v0;
                *(float2*)(Cout + (size_t)(m0 + 8) * ND + n) = v1;
            }
        }
}

// ---------------------------------------------------------------------------
// Flash attention, fp32 (unchanged math). Writes [B,S,D].
// ---------------------------------------------------------------------------
#define ATTN_SMEM_FLOATS (64*64 + 64*68 + 64*64)

__global__ __launch_bounds__(256) void attn_kernel(const int* __restrict__ valid_lens)
{
    extern __shared__ float smf[];
    float (*Qt) [64] = (float(*)[64]) smf;
    float (*KtP)[68] = (float(*)[68])(smf + 64*64);
    float (*Vs) [64] = (float(*)[64])(smf + 64*64 + 64*68);

    const int tid = threadIdx.x;
    const int tx  = tid & 15, ty = tid >> 4;
    const int qb  = blockIdx.x;
    const int bh  = blockIdx.y;
    const int bb  = bh >> 4;
    const int hh  = bh & 15;
    const int vlen = valid_lens[bb];
    const int nkb  = (vlen + 63) >> 6;

    const float* Qp = g_Q + (size_t)bh * NS * NDH;
    const float* Kp = g_K + (size_t)bh * NS * NDH;
    const float* Vp = g_V + (size_t)bh * NS * NDH;

    const float qscale = 0.125f;
    #pragma unroll
    for (int l = 0; l < 4; l++) {
        int f = tid + l * 256;
        int r = f >> 4, c4 = f & 15;
        float4 v = *(const float4*)(Qp + (size_t)(qb * 64 + r) * NDH + c4 * 4);
        Qt[c4*4+0][r] = v.x * qscale; Qt[c4*4+1][r] = v.y * qscale;
        Qt[c4*4+2][r] = v.z * qscale; Qt[c4*4+3][r] = v.w * qscale;
    }

    float m_i[4], l_i[4], o[4][4];
    #pragma unroll
    for (int i = 0; i < 4; i++) {
        m_i[i] = -1e30f; l_i[i] = 0.f;
        #pragma unroll
        for (int j = 0; j < 4; j++) o[i][j] = 0.f;
    }

    for (int kb = 0; kb < nkb; kb++) {
        __syncthreads();
        #pragma unroll
        for (int l = 0; l < 4; l++) {
            int f = tid + l * 256;
            int r = f >> 4, c4 = f & 15;
            float4 kv = *(const float4*)(Kp + (size_t)(kb * 64 + r) * NDH + c4 * 4);
            KtP[c4*4+0][r] = kv.x; KtP[c4*4+1][r] = kv.y;
            KtP[c4*4+2][r] = kv.z; KtP[c4*4+3][r] = kv.w;
            *(float4*)&Vs[r][c4*4] =
                *(const float4*)(Vp + (size_t)(kb * 64 + r) * NDH + c4 * 4);
        }
        __syncthreads();

        float sc[4][4];
        #pragma unroll
        for (int i = 0; i < 4; i++)
            #pragma unroll
            for (int j = 0; j < 4; j++) sc[i][j] = 0.f;
        #pragma unroll 16
        for (int d = 0; d < 64; d++) {
            float4 a  = *(float4*)&Qt[d][ty*4];
            float4 bk = *(float4*)&KtP[d][tx*4];
            sc[0][0] += a.x*bk.x; sc[0][1] += a.x*bk.y; sc[0][2] += a.x*bk.z; sc[0][3] += a.x*bk.w;
            sc[1][0] += a.y*bk.x; sc[1][1] += a.y*bk.y; sc[1][2] += a.y*bk.z; sc[1][3] += a.y*bk.w;
            sc[2][0] += a.z*bk.x; sc[2][1] += a.z*bk.y; sc[2][2] += a.z*bk.z; sc[2][3] += a.z*bk.w;
            sc[3][0] += a.w*bk.x; sc[3][1] += a.w*bk.y; sc[3][2] += a.w*bk.z; sc[3][3] += a.w*bk.w;
        }

        int cbase = kb * 64 + tx * 4;
        if (cbase + 3 >= vlen) {
            #pragma unroll
            for (int j = 0; j < 4; j++)
                if (cbase + j >= vlen) {
                    #pragma unroll
                    for (int i = 0; i < 4; i++) sc[i][j] = -1e30f;
                }
        }

        #pragma unroll
        for (int i = 0; i < 4; i++) {
            float mx = fmaxf(fmaxf(sc[i][0], sc[i][1]), fmaxf(sc[i][2], sc[i][3]));
            #pragma unroll
            for (int off = 8; off > 0; off >>= 1)
                mx = fmaxf(mx, __shfl_xor_sync(0xffffffffu, mx, off));
            float mnew  = fmaxf(m_i[i], mx);
            float alpha = __expf(m_i[i] - mnew);
            m_i[i] = mnew;
            float s = 0.f;
            #pragma unroll
            for (int j = 0; j < 4; j++) {
                float p = __expf(sc[i][j] - mnew);
                sc[i][j] = p; s += p;
            }
            #pragma unroll
            for (int off = 8; off > 0; off >>= 1)
                s += __shfl_xor_sync(0xffffffffu, s, off);
            l_i[i] = l_i[i] * alpha + s;
            #pragma unroll
            for (int j = 0; j < 4; j++) o[i][j] *= alpha;
        }

        __syncthreads();
        #pragma unroll
        for (int j = 0; j < 4; j++)
            #pragma unroll
            for (int i = 0; i < 4; i++)
                KtP[tx*4 + j][ty*4 + i] = sc[i][j];
        __syncthreads();

        #pragma unroll 16
        for (int j = 0; j < 64; j++) {
            float4 p  = *(float4*)&KtP[j][ty*4];
            float4 vv = *(float4*)&Vs[j][tx*4];
            o[0][0] += p.x*vv.x; o[0][1] += p.x*vv.y; o[0][2] += p.x*vv.z; o[0][3] += p.x*vv.w;
            o[1][0] += p.y*vv.x; o[1][1] += p.y*vv.y; o[1][2] += p.y*vv.z; o[1][3] += p.y*vv.w;
            o[2][0] += p.z*vv.x; o[2][1] += p.z*vv.y; o[2][2] += p.z*vv.z; o[2][3] += p.z*vv.w;
            o[3][0] += p.w*vv.x; o[3][1] += p.w*vv.y; o[3][2] += p.w*vv.z; o[3][3] += p.w*vv.w;
        }
    }

    #pragma unroll
    for (int i = 0; i < 4; i++) {
        float inv = 1.f / l_i[i];
        float4 rr = make_float4(o[i][0]*inv, o[i][1]*inv, o[i][2]*inv, o[i][3]*inv);
        *(float4*)(g_AO + (size_t)(bb * NS + qb * 64 + ty * 4 + i) * ND + hh * NDH + tx * 4) = rr;
    }
}

// ---------------------------------------------------------------------------
extern "C" void kernel_launch(void* const* d_in, const int* in_sizes, int n_in,
                              void* d_out, int out_size)
{
    const float* q  = (const float*)d_in[0];
    const float* k  = (const float*)d_in[1];
    const float* v  = (const float*)d_in[2];
    const int*   vl = (const int*)  d_in[3];
    const float* Wq = (const float*)d_in[4];
    const float* Wk = (const float*)d_in[5];
    const float* Wv = (const float*)d_in[6];
    const float* Wo = (const float*)d_in[7];
    float* out = (float*)d_out;

    cudaFuncSetAttribute(attn_kernel, cudaFuncAttributeMaxDynamicSharedMemorySize,
                         ATTN_SMEM_FLOATS * (int)sizeof(float));
    cudaFuncSetAttribute(gemm_mma_kernel, cudaFuncAttributeMaxDynamicSharedMemorySize,
                         GEMM_SMEM);

    // 1) W transpose + split
    wsplit_kernel<<<dim3(32, 32, 4), 256>>>(Wq, Wk, Wv, Wo);

    // 2) Q/K/V projections on HMMA (head-major outputs)
    gemm_mma_kernel<<<dim3(ND / 128, (NB * NS) / 128, 3), 256, GEMM_SMEM>>>(
        q, k, v, out, 0);

    // 3) flash attention (fp32), writes [B,S,D]
    attn_kernel<<<dim3(NS / 64, NB * NH), 256, ATTN_SMEM_FLOATS * (int)sizeof(float)>>>(vl);

    // 4) output projection on HMMA
    gemm_mma_kernel<<<dim3(ND / 128, (NB * NS) / 128, 1), 256, GEMM_SMEM>>>(
        q, q, q, out, 1);
}

// round 4
// speedup vs baseline: 2.7102x; 1.7421x over previous
#include <cuda_runtime.h>
#include <cuda_bf16.h>
#include <stdint.h>

#define NB  2
#define NS  2048
#define ND  1024
#define NH  16
#define NDH 64

// Scratch (allocation-free rule: __device__ globals).
__device__ float g_AO[NB*NS*ND];              // attention out, [B*S, D] row-major
__device__ __nv_bfloat16 g_Whi[4u << 20];     // 4 x W^T hi: [n][k] k-major
__device__ __nv_bfloat16 g_Wlo[4u << 20];     // 4 x W^T lo
// Q/K/V split bf16, head-major [B,H,S,DH]
__device__ __nv_bfloat16 g_Qhi[NB*NH*NS*NDH], g_Qlo[NB*NH*NS*NDH];
__device__ __nv_bfloat16 g_Khi[NB*NH*NS*NDH], g_Klo[NB*NH*NS*NDH];
__device__ __nv_bfloat16 g_Vhi[NB*NH*NS*NDH], g_Vlo[NB*NH*NS*NDH];

// ---------------------------------------------------------------------------
// helpers
// ---------------------------------------------------------------------------
__device__ __forceinline__ uint32_t smem_u32(const void* p) {
    uint32_t a;
    asm("{ .reg .u64 t; cvta.to.shared.u64 t, %1; cvt.u32.u64 %0, t; }" : "=r"(a) : "l"(p));
    return a;
}
__device__ __forceinline__ void cpasync16(uint32_t dst, const void* src) {
    asm volatile("cp.async.cg.shared.global [%0], [%1], 16;" :: "r"(dst), "l"(src));
}
#define CP_COMMIT() asm volatile("cp.async.commit_group;" ::: "memory")
#define CP_WAIT0()  asm volatile("cp.async.wait_group 0;" ::: "memory")

#define LDSM_X4(r0, r1, r2, r3, addr)                                          \
    asm volatile("ldmatrix.sync.aligned.m8n8.x4.shared.b16 {%0,%1,%2,%3}, [%4];" \
        : "=r"(r0), "=r"(r1), "=r"(r2), "=r"(r3) : "r"(addr))
#define LDSM_X4_T(r0, r1, r2, r3, addr)                                        \
    asm volatile("ldmatrix.sync.aligned.m8n8.x4.trans.shared.b16 {%0,%1,%2,%3}, [%4];" \
        : "=r"(r0), "=r"(r1), "=r"(r2), "=r"(r3) : "r"(addr))

#define MMA_BF16(d, a, b)                                                      \
    asm volatile("mma.sync.aligned.m16n8k16.row.col.f32.bf16.bf16.f32 "        \
        "{%0,%1,%2,%3},{%4,%5,%6,%7},{%8,%9},{%0,%1,%2,%3};"                   \
        : "+f"((d)[0]), "+f"((d)[1]), "+f"((d)[2]), "+f"((d)[3])               \
        : "r"((a)[0]), "r"((a)[1]), "r"((a)[2]), "r"((a)[3]),                  \
          "r"((b)[0]), "r"((b)[1]))

__device__ __forceinline__ void split2(float a, float b, uint32_t& hi, uint32_t& lo) {
    __nv_bfloat16 ha = __float2bfloat16(a), hb = __float2bfloat16(b);
    float ra = a - __bfloat162float(ha), rb = b - __bfloat162float(hb);
    hi = (uint32_t)__bfloat16_as_ushort(ha) | ((uint32_t)__bfloat16_as_ushort(hb) << 16);
    __nv_bfloat16 la = __float2bfloat16(ra), lb = __float2bfloat16(rb);
    lo = (uint32_t)__bfloat16_as_ushort(la) | ((uint32_t)__bfloat16_as_ushort(lb) << 16);
}

// ---------------------------------------------------------------------------
// W transpose + fp32 -> (bf16 hi, bf16 lo). Out[n][k] = W[k][n].
// ---------------------------------------------------------------------------
__global__ __launch_bounds__(256) void wsplit_kernel(
    const float* __restrict__ W0, const float* __restrict__ W1,
    const float* __restrict__ W2, const float* __restrict__ W3)
{
    __shared__ float t[32][33];
    const float* W = (blockIdx.z == 0) ? W0 : (blockIdx.z == 1) ? W1 :
                     (blockIdx.z == 2) ? W2 : W3;
    __nv_bfloat16* Ohi = g_Whi + ((size_t)blockIdx.z << 20);
    __nv_bfloat16* Olo = g_Wlo + ((size_t)blockIdx.z << 20);

    int tx = threadIdx.x & 31, ty = threadIdx.x >> 5;
    int n0 = blockIdx.x * 32, k0 = blockIdx.y * 32;

    #pragma unroll
    for (int i = 0; i < 4; i++)
        t[ty + i*8][tx] = W[(size_t)(k0 + ty + i*8) * ND + n0 + tx];
    __syncthreads();
    #pragma unroll
    for (int i = 0; i < 4; i++) {
        float v = t[tx][ty + i*8];
        __nv_bfloat16 h = __float2bfloat16(v);
        __nv_bfloat16 l = __float2bfloat16(v - __bfloat162float(h));
        size_t idx = (size_t)(n0 + ty + i*8) * ND + k0 + tx;
        Ohi[idx] = h; Olo[idx] = l;
    }
}

// ---------------------------------------------------------------------------
// HMMA split-bf16 GEMM: C[4096,1024] = A[4096,1024] @ W[1024,1024]
// CTA 128x128, BK=64, double-buffered, 8 warps (32m x 64n each).
// mode 0: out = split bf16 hi/lo head-major (Q scaled 0.125). mode 1: fp32 out.
// ---------------------------------------------------------------------------
#define BUF_BYTES 65536
#define OFS_AHI 0
#define OFS_ALO 16384
#define OFS_BHI 32768
#define OFS_BLO 49152
#define GEMM_SMEM (2 * BUF_BYTES)

__global__ __launch_bounds__(256, 1) void gemm_mma_kernel(
    const float* __restrict__ Xq, const float* __restrict__ Xk,
    const float* __restrict__ Xv, float* __restrict__ Cout, int mode)
{
    extern __shared__ char smc[];
    const uint32_t sb = smem_u32(smc);
    const int tid  = threadIdx.x;
    const int wid  = tid >> 5, lane = tid & 31;
    const int z    = blockIdx.z;

    const float* A;
    const __nv_bfloat16 *Whi, *Wlo;
    __nv_bfloat16 *Ohi = 0, *Olo = 0;
    float osc = 1.f;
    if (mode == 0) {
        A = (z == 0) ? Xq : (z == 1) ? Xk : Xv;
        Whi = g_Whi + ((size_t)z << 20);
        Wlo = g_Wlo + ((size_t)z << 20);
        Ohi = (z == 0) ? g_Qhi : (z == 1) ? g_Khi : g_Vhi;
        Olo = (z == 0) ? g_Qlo : (z == 1) ? g_Klo : g_Vlo;
        if (z == 0) osc = 0.125f;
    } else {
        A = g_AO;
        Whi = g_Whi + ((size_t)3 << 20);
        Wlo = g_Wlo + ((size_t)3 << 20);
    }
    const int bM = blockIdx.y * 128, bN = blockIdx.x * 128;
    const int warp_m = (wid & 3) * 32, warp_n = (wid >> 2) * 64;

    float acc[16][4];
    #pragma unroll
    for (int i = 0; i < 16; i++)
        #pragma unroll
        for (int j = 0; j < 4; j++) acc[i][j] = 0.f;

    float4 ar[8];

    auto ldgA = [&](int s) {
        #pragma unroll
        for (int l = 0; l < 8; l++) {
            int f = tid + l * 256;
            ar[l] = *(const float4*)(A + (size_t)(bM + (f >> 4)) * ND + s * 64 + (f & 15) * 4);
        }
    };
    auto stsA = [&](int buf) {
        #pragma unroll
        for (int l = 0; l < 8; l++) {
            int f = tid + l * 256;
            int row = f >> 4, c4 = f & 15;
            uint2 hi, lo;
            split2(ar[l].x, ar[l].y, hi.x, lo.x);
            split2(ar[l].z, ar[l].w, hi.y, lo.y);
            uint32_t off = row * 128 + ((c4 * 8) ^ ((row & 7) * 16));
            *(uint2*)(smc + buf * BUF_BYTES + OFS_AHI + off) = hi;
            *(uint2*)(smc + buf * BUF_BYTES + OFS_ALO + off) = lo;
        }
    };
    auto cpB = [&](int s, int buf) {
        uint32_t base = sb + buf * BUF_BYTES;
        #pragma unroll
        for (int l = 0; l < 8; l++) {
            int f = tid + l * 256;
            int arr = f >> 10;
            int r   = (f >> 3) & 127;
            int c   = f & 7;
            const __nv_bfloat16* src =
                (arr ? Wlo : Whi) + (size_t)(bN + r) * ND + s * 64 + c * 8;
            uint32_t dst = base + (arr ? OFS_BLO : OFS_BHI)
                         + r * 128 + ((c * 16) ^ ((r & 7) * 16));
            cpasync16(dst, src);
        }
        CP_COMMIT();
    };

    ldgA(0);
    stsA(0);
    cpB(0, 0);

    for (int s = 0; s < 16; s++) {
        const int buf = s & 1;
        if (s + 1 < 16) ldgA(s + 1);
        CP_WAIT0();
        __syncthreads();
        if (s + 1 < 16) cpB(s + 1, buf ^ 1);

        const uint32_t aHi = sb + buf * BUF_BYTES + OFS_AHI;
        const uint32_t aLo = sb + buf * BUF_BYTES + OFS_ALO;
        const uint32_t bHi = sb + buf * BUF_BYTES + OFS_BHI;
        const uint32_t bLo = sb + buf * BUF_BYTES + OFS_BLO;

        #pragma unroll
        for (int kk = 0; kk < 4; kk++) {
            const int k0 = kk * 16;
            uint32_t ah[2][4], al[2][4], bh[8][2], bl[8][2];
            #pragma unroll
            for (int mt = 0; mt < 2; mt++) {
                int row = warp_m + mt * 16 + (lane & 15);
                uint32_t off = row * 128 + ((k0 * 2 + (lane >> 4) * 16) ^ ((row & 7) * 16));
                LDSM_X4(ah[mt][0], ah[mt][1], ah[mt][2], ah[mt][3], aHi + off);
                LDSM_X4(al[mt][0], al[mt][1], al[mt][2], al[mt][3], aLo + off);
            }
            #pragma unroll
            for (int p = 0; p < 4; p++) {
                int n = warp_n + p * 16 + (lane & 7) + ((lane >> 4) << 3);
                uint32_t off = n * 128 + ((k0 * 2 + ((lane >> 3) & 1) * 16) ^ ((n & 7) * 16));
                LDSM_X4(bh[p*2][0], bh[p*2][1], bh[p*2+1][0], bh[p*2+1][1], bHi + off);
                LDSM_X4(bl[p*2][0], bl[p*2][1], bl[p*2+1][0], bl[p*2+1][1], bLo + off);
            }
            #pragma unroll
            for (int mt = 0; mt < 2; mt++)
                #pragma unroll
                for (int nt = 0; nt < 8; nt++) {
                    MMA_BF16(acc[mt*8+nt], ah[mt], bh[nt]);
                    MMA_BF16(acc[mt*8+nt], ah[mt], bl[nt]);
                    MMA_BF16(acc[mt*8+nt], al[mt], bh[nt]);
                }
        }
        if (s + 1 < 16) stsA(buf ^ 1);
    }

    #pragma unroll
    for (int mt = 0; mt < 2; mt++)
        #pragma unroll
        for (int nt = 0; nt < 8; nt++) {
            int m0 = bM + warp_m + mt * 16 + (lane >> 2);
            int n  = bN + warp_n + nt * 8 + (lane & 3) * 2;
            float* a4 = acc[mt*8+nt];
            if (mode == 0) {
                int h = n >> 6, dh = n & 63;
                int b0 = m0 >> 11, s0 = m0 & 2047;
                int m1 = m0 + 8, b1 = m1 >> 11, s1 = m1 & 2047;
                size_t i0 = ((size_t)(b0 * NH + h) * NS + s0) * NDH + dh;
                size_t i1 = ((size_t)(b1 * NH + h) * NS + s1) * NDH + dh;
                uint32_t h0, l0, h1, l1;
                split2(a4[0] * osc, a4[1] * osc, h0, l0);
                split2(a4[2] * osc, a4[3] * osc, h1, l1);
                *(uint32_t*)(Ohi + i0) = h0; *(uint32_t*)(Olo + i0) = l0;
                *(uint32_t*)(Ohi + i1) = h1; *(uint32_t*)(Olo + i1) = l1;
            } else {
                *(float2*)(Cout + (size_t)m0 * ND + n)       = make_float2(a4[0], a4[1]);
                *(float2*)(Cout + (size_t)(m0 + 8) * ND + n) = make_float2(a4[2], a4[3]);
            }
        }
}

// ---------------------------------------------------------------------------
// Flash attention on HMMA, split-bf16, 3-pass QK^T and PV.
// CTA = 128 q x 64 k, 8 warps (16q x 64k each), double-buffered K/V hi/lo.
// ---------------------------------------------------------------------------
#define ATT_BUF  32768
#define ATT_SMEM (2 * ATT_BUF)

__global__ __launch_bounds__(256, 1) void attn_mma_kernel(const int* __restrict__ valid_lens)
{
    extern __shared__ char smc[];
    const uint32_t sb = smem_u32(smc);
    const int tid = threadIdx.x, wid = tid >> 5, lane = tid & 31;
    const int qb = blockIdx.x, bh = blockIdx.y;
    const int bb = bh >> 4, hh = bh & 15;
    const int vlen = valid_lens[bb];
    const int nkb  = (vlen + 63) >> 6;

    const size_t hb = (size_t)bh * NS * NDH;
    const __nv_bfloat16 *Qhi = g_Qhi + hb, *Qlo = g_Qlo + hb;
    const __nv_bfloat16 *Khi = g_Khi + hb, *Klo = g_Klo + hb;
    const __nv_bfloat16 *Vhi = g_Vhi + hb, *Vlo = g_Vlo + hb;

    const int r = lane >> 2, c2 = (lane & 3) * 2;

    // Q fragments (loop-invariant), direct from gmem: a0=(r,2c) a1=(r+8,2c) a2=(r,2c+8) a3=(r+8,2c+8)
    uint32_t qh[4][4], ql[4][4];
    {
        const int q0 = qb * 128 + wid * 16;
        #pragma unroll
        for (int t = 0; t < 4; t++) {
            int k0 = t * 16;
            qh[t][0] = *(const uint32_t*)(Qhi + (size_t)(q0 + r    ) * NDH + k0 + c2);
            qh[t][1] = *(const uint32_t*)(Qhi + (size_t)(q0 + r + 8) * NDH + k0 + c2);
            qh[t][2] = *(const uint32_t*)(Qhi + (size_t)(q0 + r    ) * NDH + k0 + c2 + 8);
            qh[t][3] = *(const uint32_t*)(Qhi + (size_t)(q0 + r + 8) * NDH + k0 + c2 + 8);
            ql[t][0] = *(const uint32_t*)(Qlo + (size_t)(q0 + r    ) * NDH + k0 + c2);
            ql[t][1] = *(const uint32_t*)(Qlo + (size_t)(q0 + r + 8) * NDH + k0 + c2);
            ql[t][2] = *(const uint32_t*)(Qlo + (size_t)(q0 + r    ) * NDH + k0 + c2 + 8);
            ql[t][3] = *(const uint32_t*)(Qlo + (size_t)(q0 + r + 8) * NDH + k0 + c2 + 8);
        }
    }

    float m_i[2] = {-1e30f, -1e30f}, l_i[2] = {0.f, 0.f};
    float o[8][4];
    #pragma unroll
    for (int i = 0; i < 8; i++)
        #pragma unroll
        for (int j = 0; j < 4; j++) o[i][j] = 0.f;

    auto cpKV = [&](int kb, int buf) {
        #pragma unroll
        for (int l = 0; l < 8; l++) {
            int f   = tid + l * 256;
            int arr = f >> 9;                 // 0:Khi 1:Klo 2:Vhi 3:Vlo (8KB each)
            int rr  = (f >> 3) & 63;
            int cc  = f & 7;
            const __nv_bfloat16* srcb =
                (arr == 0) ? Khi : (arr == 1) ? Klo : (arr == 2) ? Vhi : Vlo;
            const void* src = srcb + (size_t)(kb * 64 + rr) * NDH + cc * 8;
            uint32_t dst = sb + buf * ATT_BUF + arr * 8192
                         + rr * 128 + ((cc * 16) ^ ((rr & 7) * 16));
            cpasync16(dst, src);
        }
        CP_COMMIT();
    };

    cpKV(0, 0);

    for (int kb = 0; kb < nkb; kb++) {
        const int buf = kb & 1;
        CP_WAIT0();
        __syncthreads();
        if (kb + 1 < nkb) cpKV(kb + 1, buf ^ 1);

        const uint32_t kHi = sb + buf * ATT_BUF;
        const uint32_t kLo = kHi + 8192;
        const uint32_t vHi = kHi + 16384;
        const uint32_t vLo = kHi + 24576;

        // ---- S = Q K^T (3-pass split) ----
        float s[8][4];
        #pragma unroll
        for (int i = 0; i < 8; i++)
            #pragma unroll
            for (int j = 0; j < 4; j++) s[i][j] = 0.f;

        #pragma unroll
        for (int t = 0; t < 4; t++) {
            uint32_t kh[8][2], kl[8][2];
            #pragma unroll
            for (int p = 0; p < 4; p++) {
                int n = p * 16 + (lane & 7) + ((lane >> 4) << 3);
                uint32_t off = n * 128 + ((t * 32 + ((lane >> 3) & 1) * 16) ^ ((n & 7) * 16));
                LDSM_X4(kh[p*2][0], kh[p*2][1], kh[p*2+1][0], kh[p*2+1][1], kHi + off);
                LDSM_X4(kl[p*2][0], kl[p*2][1], kl[p*2+1][0], kl[p*2+1][1], kLo + off);
            }
            #pragma unroll
            for (int nt = 0; nt < 8; nt++) {
                MMA_BF16(s[nt], qh[t], kh[nt]);
                MMA_BF16(s[nt], ql[t], kh[nt]);
                MMA_BF16(s[nt], qh[t], kl[nt]);
            }
        }

        // ---- mask tail columns ----
        if (kb == nkb - 1) {
            int cb = kb * 64 + c2;
            #pragma unroll
            for (int nt = 0; nt < 8; nt++) {
                int c0g = cb + nt * 8;
                if (c0g     >= vlen) { s[nt][0] = -1e30f; s[nt][2] = -1e30f; }
                if (c0g + 1 >= vlen) { s[nt][1] = -1e30f; s[nt][3] = -1e30f; }
            }
        }

        // ---- online softmax (rows r and r+8; quad = lanes sharing row) ----
        float mx0 = -1e30f, mx1 = -1e30f;
        #pragma unroll
        for (int nt = 0; nt < 8; nt++) {
            mx0 = fmaxf(mx0, fmaxf(s[nt][0], s[nt][1]));
            mx1 = fmaxf(mx1, fmaxf(s[nt][2], s[nt][3]));
        }
        mx0 = fmaxf(mx0, __shfl_xor_sync(0xffffffffu, mx0, 1));
        mx0 = fmaxf(mx0, __shfl_xor_sync(0xffffffffu, mx0, 2));
        mx1 = fmaxf(mx1, __shfl_xor_sync(0xffffffffu, mx1, 1));
        mx1 = fmaxf(mx1, __shfl_xor_sync(0xffffffffu, mx1, 2));

        float mn0 = fmaxf(m_i[0], mx0), mn1 = fmaxf(m_i[1], mx1);
        float a0 = __expf(m_i[0] - mn0), a1 = __expf(m_i[1] - mn1);
        m_i[0] = mn0; m_i[1] = mn1;

        float sum0 = 0.f, sum1 = 0.f;
        #pragma unroll
        for (int nt = 0; nt < 8; nt++) {
            s[nt][0] = __expf(s[nt][0] - mn0); sum0 += s[nt][0];
            s[nt][1] = __expf(s[nt][1] - mn0); sum0 += s[nt][1];
            s[nt][2] = __expf(s[nt][2] - mn1); sum1 += s[nt][2];
            s[nt][3] = __expf(s[nt][3] - mn1); sum1 += s[nt][3];
        }
        sum0 += __shfl_xor_sync(0xffffffffu, sum0, 1);
        sum0 += __shfl_xor_sync(0xffffffffu, sum0, 2);
        sum1 += __shfl_xor_sync(0xffffffffu, sum1, 1);
        sum1 += __shfl_xor_sync(0xffffffffu, sum1, 2);
        l_i[0] = l_i[0] * a0 + sum0;
        l_i[1] = l_i[1] * a1 + sum1;
        #pragma unroll
        for (int nt = 0; nt < 8; nt++) {
            o[nt][0] *= a0; o[nt][1] *= a0;
            o[nt][2] *= a1; o[nt][3] *= a1;
        }

        // ---- O += P V (3-pass split; P packed from S fragments) ----
        #pragma unroll
        for (int t = 0; t < 4; t++) {
            uint32_t ph[4], pl[4];
            split2(s[2*t  ][0], s[2*t  ][1], ph[0], pl[0]);
            split2(s[2*t  ][2], s[2*t  ][3], ph[1], pl[1]);
            split2(s[2*t+1][0], s[2*t+1][1], ph[2], pl[2]);
            split2(s[2*t+1][2], s[2*t+1][3], ph[3], pl[3]);

            uint32_t vh[8][2], vl[8][2];
            #pragma unroll
            for (int p = 0; p < 4; p++) {
                int rowb = t * 16 + (lane & 15);
                uint32_t off = rowb * 128 + ((p * 32 + (lane >> 4) * 16) ^ ((rowb & 7) * 16));
                LDSM_X4_T(vh[p*2][0], vh[p*2][1], vh[p*2+1][0], vh[p*2+1][1], vHi + off);
                LDSM_X4_T(vl[p*2][0], vl[p*2][1], vl[p*2+1][0], vl[p*2+1][1], vLo + off);
            }
            #pragma unroll
            for (int nt = 0; nt < 8; nt++) {
                MMA_BF16(o[nt], ph, vh[nt]);
                MMA_BF16(o[nt], pl, vh[nt]);
                MMA_BF16(o[nt], ph, vl[nt]);
            }
        }
    }

    // ---- epilogue: write [B,S,D] fp32 ----
    const float inv0 = 1.f / l_i[0], inv1 = 1.f / l_i[1];
    const int row0 = qb * 128 + wid * 16 + r;
    float* out0 = g_AO + (size_t)(bb * NS + row0    ) * ND + hh * 64;
    float* out1 = g_AO + (size_t)(bb * NS + row0 + 8) * ND + hh * 64;
    #pragma unroll
    for (int nt = 0; nt < 8; nt++) {
        *(float2*)(out0 + nt * 8 + c2) = make_float2(o[nt][0] * inv0, o[nt][1] * inv0);
        *(float2*)(out1 + nt * 8 + c2) = make_float2(o[nt][2] * inv1, o[nt][3] * inv1);
    }
}

// ---------------------------------------------------------------------------
extern "C" void kernel_launch(void* const* d_in, const int* in_sizes, int n_in,
                              void* d_out, int out_size)
{
    const float* q  = (const float*)d_in[0];
    const float* k  = (const float*)d_in[1];
    const float* v  = (const float*)d_in[2];
    const int*   vl = (const int*)  d_in[3];
    const float* Wq = (const float*)d_in[4];
    const float* Wk = (const float*)d_in[5];
    const float* Wv = (const float*)d_in[6];
    const float* Wo = (const float*)d_in[7];
    float* out = (float*)d_out;

    cudaFuncSetAttribute(gemm_mma_kernel, cudaFuncAttributeMaxDynamicSharedMemorySize,
                         GEMM_SMEM);
    cudaFuncSetAttribute(attn_mma_kernel, cudaFuncAttributeMaxDynamicSharedMemorySize,
                         ATT_SMEM);

    // 1) W transpose + split
    wsplit_kernel<<<dim3(32, 32, 4), 256>>>(Wq, Wk, Wv, Wo);

    // 2) Q/K/V projections -> split bf16 head-major (Q pre-scaled)
    gemm_mma_kernel<<<dim3(ND / 128, (NB * NS) / 128, 3), 256, GEMM_SMEM>>>(
        q, k, v, out, 0);

    // 3) flash attention on HMMA, writes [B,S,D] fp32
    attn_mma_kernel<<<dim3(NS / 128, NB * NH), 256, ATT_SMEM>>>(vl);

    // 4) output projection
    gemm_mma_kernel<<<dim3(ND / 128, (NB * NS) / 128, 1), 256, GEMM_SMEM>>>(
        q, q, q, out, 1);
}

// round 5
// speedup vs baseline: 2.7118x; 1.0006x over previous
#include <cuda_runtime.h>
#include <cuda_bf16.h>
#include <stdint.h>

#define NB  2
#define NS  2048
#define ND  1024
#define NH  16
#define NDH 64

// Scratch (allocation-free rule: __device__ globals).
__device__ float g_AO[NB*NS*ND];              // attention out, [B*S, D] row-major
__device__ __nv_bfloat16 g_Whi[4u << 20];     // 4 x W^T hi: [n][k] k-major
__device__ __nv_bfloat16 g_Wlo[4u << 20];     // 4 x W^T lo
// Q/K/V split bf16, head-major [B,H,S,DH]
__device__ __nv_bfloat16 g_Qhi[NB*NH*NS*NDH], g_Qlo[NB*NH*NS*NDH];
__device__ __nv_bfloat16 g_Khi[NB*NH*NS*NDH], g_Klo[NB*NH*NS*NDH];
__device__ __nv_bfloat16 g_Vhi[NB*NH*NS*NDH], g_Vlo[NB*NH*NS*NDH];

// ---------------------------------------------------------------------------
// helpers
// ---------------------------------------------------------------------------
__device__ __forceinline__ uint32_t smem_u32(const void* p) {
    uint32_t a;
    asm("{ .reg .u64 t; cvta.to.shared.u64 t, %1; cvt.u32.u64 %0, t; }" : "=r"(a) : "l"(p));
    return a;
}
__device__ __forceinline__ void cpasync16(uint32_t dst, const void* src) {
    asm volatile("cp.async.cg.shared.global [%0], [%1], 16;" :: "r"(dst), "l"(src));
}
#define CP_COMMIT() asm volatile("cp.async.commit_group;" ::: "memory")
#define CP_WAIT0()  asm volatile("cp.async.wait_group 0;" ::: "memory")

#define LDSM_X4(r0, r1, r2, r3, addr)                                          \
    asm volatile("ldmatrix.sync.aligned.m8n8.x4.shared.b16 {%0,%1,%2,%3}, [%4];" \
        : "=r"(r0), "=r"(r1), "=r"(r2), "=r"(r3) : "r"(addr))
#define LDSM_X4_T(r0, r1, r2, r3, addr)                                        \
    asm volatile("ldmatrix.sync.aligned.m8n8.x4.trans.shared.b16 {%0,%1,%2,%3}, [%4];" \
        : "=r"(r0), "=r"(r1), "=r"(r2), "=r"(r3) : "r"(addr))

#define MMA_BF16(d, a, b)                                                      \
    asm volatile("mma.sync.aligned.m16n8k16.row.col.f32.bf16.bf16.f32 "        \
        "{%0,%1,%2,%3},{%4,%5,%6,%7},{%8,%9},{%0,%1,%2,%3};"                   \
        : "+f"((d)[0]), "+f"((d)[1]), "+f"((d)[2]), "+f"((d)[3])               \
        : "r"((a)[0]), "r"((a)[1]), "r"((a)[2]), "r"((a)[3]),                  \
          "r"((b)[0]), "r"((b)[1]))

__device__ __forceinline__ void split2(float a, float b, uint32_t& hi, uint32_t& lo) {
    __nv_bfloat16 ha = __float2bfloat16(a), hb = __float2bfloat16(b);
    float ra = a - __bfloat162float(ha), rb = b - __bfloat162float(hb);
    hi = (uint32_t)__bfloat16_as_ushort(ha) | ((uint32_t)__bfloat16_as_ushort(hb) << 16);
    __nv_bfloat16 la = __float2bfloat16(ra), lb = __float2bfloat16(rb);
    lo = (uint32_t)__bfloat16_as_ushort(la) | ((uint32_t)__bfloat16_as_ushort(lb) << 16);
}

// ---------------------------------------------------------------------------
// W transpose + fp32 -> (bf16 hi, bf16 lo). Out[n][k] = W[k][n].
// ---------------------------------------------------------------------------
__global__ __launch_bounds__(256) void wsplit_kernel(
    const float* __restrict__ W0, const float* __restrict__ W1,
    const float* __restrict__ W2, const float* __restrict__ W3)
{
    __shared__ float t[32][33];
    const float* W = (blockIdx.z == 0) ? W0 : (blockIdx.z == 1) ? W1 :
                     (blockIdx.z == 2) ? W2 : W3;
    __nv_bfloat16* Ohi = g_Whi + ((size_t)blockIdx.z << 20);
    __nv_bfloat16* Olo = g_Wlo + ((size_t)blockIdx.z << 20);

    int tx = threadIdx.x & 31, ty = threadIdx.x >> 5;
    int n0 = blockIdx.x * 32, k0 = blockIdx.y * 32;

    #pragma unroll
    for (int i = 0; i < 4; i++)
        t[ty + i*8][tx] = W[(size_t)(k0 + ty + i*8) * ND + n0 + tx];
    __syncthreads();
    #pragma unroll
    for (int i = 0; i < 4; i++) {
        float v = t[tx][ty + i*8];
        __nv_bfloat16 h = __float2bfloat16(v);
        __nv_bfloat16 l = __float2bfloat16(v - __bfloat162float(h));
        size_t idx = (size_t)(n0 + ty + i*8) * ND + k0 + tx;
        Ohi[idx] = h; Olo[idx] = l;
    }
}

// ---------------------------------------------------------------------------
// HMMA split-bf16 GEMM: C[4096,1024] = A[4096,1024] @ W[1024,1024]
// CTA 128x128, BK=64, double-buffered, 8 warps (32m x 64n each).
// Pass-major MMA issue order (RAW chain distance = 16 accumulators).
// ---------------------------------------------------------------------------
#define BUF_BYTES 65536
#define OFS_AHI 0
#define OFS_ALO 16384
#define OFS_BHI 32768
#define OFS_BLO 49152
#define GEMM_SMEM (2 * BUF_BYTES)

__global__ __launch_bounds__(256, 1) void gemm_mma_kernel(
    const float* __restrict__ Xq, const float* __restrict__ Xk,
    const float* __restrict__ Xv, float* __restrict__ Cout, int mode)
{
    extern __shared__ char smc[];
    const uint32_t sb = smem_u32(smc);
    const int tid  = threadIdx.x;
    const int wid  = tid >> 5, lane = tid & 31;
    const int z    = blockIdx.z;

    const float* A;
    const __nv_bfloat16 *Whi, *Wlo;
    __nv_bfloat16 *Ohi = 0, *Olo = 0;
    float osc = 1.f;
    if (mode == 0) {
        A = (z == 0) ? Xq : (z == 1) ? Xk : Xv;
        Whi = g_Whi + ((size_t)z << 20);
        Wlo = g_Wlo + ((size_t)z << 20);
        Ohi = (z == 0) ? g_Qhi : (z == 1) ? g_Khi : g_Vhi;
        Olo = (z == 0) ? g_Qlo : (z == 1) ? g_Klo : g_Vlo;
        if (z == 0) osc = 0.125f;
    } else {
        A = g_AO;
        Whi = g_Whi + ((size_t)3 << 20);
        Wlo = g_Wlo + ((size_t)3 << 20);
    }
    const int bM = blockIdx.y * 128, bN = blockIdx.x * 128;
    const int warp_m = (wid & 3) * 32, warp_n = (wid >> 2) * 64;

    float acc[16][4];
    #pragma unroll
    for (int i = 0; i < 16; i++)
        #pragma unroll
        for (int j = 0; j < 4; j++) acc[i][j] = 0.f;

    float4 ar[8];

    auto ldgA = [&](int s) {
        #pragma unroll
        for (int l = 0; l < 8; l++) {
            int f = tid + l * 256;
            ar[l] = *(const float4*)(A + (size_t)(bM + (f >> 4)) * ND + s * 64 + (f & 15) * 4);
        }
    };
    auto stsA = [&](int buf) {
        #pragma unroll
        for (int l = 0; l < 8; l++) {
            int f = tid + l * 256;
            int row = f >> 4, c4 = f & 15;
            uint2 hi, lo;
            split2(ar[l].x, ar[l].y, hi.x, lo.x);
            split2(ar[l].z, ar[l].w, hi.y, lo.y);
            uint32_t off = row * 128 + ((c4 * 8) ^ ((row & 7) * 16));
            *(uint2*)(smc + buf * BUF_BYTES + OFS_AHI + off) = hi;
            *(uint2*)(smc + buf * BUF_BYTES + OFS_ALO + off) = lo;
        }
    };
    auto cpB = [&](int s, int buf) {
        uint32_t base = sb + buf * BUF_BYTES;
        #pragma unroll
        for (int l = 0; l < 8; l++) {
            int f = tid + l * 256;
            int arr = f >> 10;
            int r   = (f >> 3) & 127;
            int c   = f & 7;
            const __nv_bfloat16* src =
                (arr ? Wlo : Whi) + (size_t)(bN + r) * ND + s * 64 + c * 8;
            uint32_t dst = base + (arr ? OFS_BLO : OFS_BHI)
                         + r * 128 + ((c * 16) ^ ((r & 7) * 16));
            cpasync16(dst, src);
        }
        CP_COMMIT();
    };

    ldgA(0);
    stsA(0);
    cpB(0, 0);

    for (int s = 0; s < 16; s++) {
        const int buf = s & 1;
        if (s + 1 < 16) ldgA(s + 1);
        CP_WAIT0();
        __syncthreads();
        if (s + 1 < 16) cpB(s + 1, buf ^ 1);

        const uint32_t aHi = sb + buf * BUF_BYTES + OFS_AHI;
        const uint32_t aLo = sb + buf * BUF_BYTES + OFS_ALO;
        const uint32_t bHi = sb + buf * BUF_BYTES + OFS_BHI;
        const uint32_t bLo = sb + buf * BUF_BYTES + OFS_BLO;

        #pragma unroll
        for (int kk = 0; kk < 4; kk++) {
            const int k0 = kk * 16;
            uint32_t ah[2][4], al[2][4], bh[8][2], bl[8][2];
            #pragma unroll
            for (int mt = 0; mt < 2; mt++) {
                int row = warp_m + mt * 16 + (lane & 15);
                uint32_t off = row * 128 + ((k0 * 2 + (lane >> 4) * 16) ^ ((row & 7) * 16));
                LDSM_X4(ah[mt][0], ah[mt][1], ah[mt][2], ah[mt][3], aHi + off);
                LDSM_X4(al[mt][0], al[mt][1], al[mt][2], al[mt][3], aLo + off);
            }
            #pragma unroll
            for (int p = 0; p < 4; p++) {
                int n = warp_n + p * 16 + (lane & 7) + ((lane >> 4) << 3);
                uint32_t off = n * 128 + ((k0 * 2 + ((lane >> 3) & 1) * 16) ^ ((n & 7) * 16));
                LDSM_X4(bh[p*2][0], bh[p*2][1], bh[p*2+1][0], bh[p*2+1][1], bHi + off);
                LDSM_X4(bl[p*2][0], bl[p*2][1], bl[p*2+1][0], bl[p*2+1][1], bLo + off);
            }
            // pass-major: 16 distinct accumulators between reuses
            #pragma unroll
            for (int mt = 0; mt < 2; mt++)
                #pragma unroll
                for (int nt = 0; nt < 8; nt++)
                    MMA_BF16(acc[mt*8+nt], ah[mt], bh[nt]);
            #pragma unroll
            for (int mt = 0; mt < 2; mt++)
                #pragma unroll
                for (int nt = 0; nt < 8; nt++)
                    MMA_BF16(acc[mt*8+nt], ah[mt], bl[nt]);
            #pragma unroll
            for (int mt = 0; mt < 2; mt++)
                #pragma unroll
                for (int nt = 0; nt < 8; nt++)
                    MMA_BF16(acc[mt*8+nt], al[mt], bh[nt]);
        }
        if (s + 1 < 16) stsA(buf ^ 1);
    }

    #pragma unroll
    for (int mt = 0; mt < 2; mt++)
        #pragma unroll
        for (int nt = 0; nt < 8; nt++) {
            int m0 = bM + warp_m + mt * 16 + (lane >> 2);
            int n  = bN + warp_n + nt * 8 + (lane & 3) * 2;
            float* a4 = acc[mt*8+nt];
            if (mode == 0) {
                int h = n >> 6, dh = n & 63;
                int b0 = m0 >> 11, s0 = m0 & 2047;
                int m1 = m0 + 8, b1 = m1 >> 11, s1 = m1 & 2047;
                size_t i0 = ((size_t)(b0 * NH + h) * NS + s0) * NDH + dh;
                size_t i1 = ((size_t)(b1 * NH + h) * NS + s1) * NDH + dh;
                uint32_t h0, l0, h1, l1;
                split2(a4[0] * osc, a4[1] * osc, h0, l0);
                split2(a4[2] * osc, a4[3] * osc, h1, l1);
                *(uint32_t*)(Ohi + i0) = h0; *(uint32_t*)(Olo + i0) = l0;
                *(uint32_t*)(Ohi + i1) = h1; *(uint32_t*)(Olo + i1) = l1;
            } else {
                *(float2*)(Cout + (size_t)m0 * ND + n)       = make_float2(a4[0], a4[1]);
                *(float2*)(Cout + (size_t)(m0 + 8) * ND + n) = make_float2(a4[2], a4[3]);
            }
        }
}

// ---------------------------------------------------------------------------
// Flash attention on HMMA, split-bf16, 3-pass QK^T and PV, pass-major order.
// CTA = 128 q x 64 k, 8 warps (16q x 64k each), double-buffered K/V hi/lo.
// ---------------------------------------------------------------------------
#define ATT_BUF  32768
#define ATT_SMEM (2 * ATT_BUF)

__global__ __launch_bounds__(256, 1) void attn_mma_kernel(const int* __restrict__ valid_lens)
{
    extern __shared__ char smc[];
    const uint32_t sb = smem_u32(smc);
    const int tid = threadIdx.x, wid = tid >> 5, lane = tid & 31;
    const int qb = blockIdx.x, bh = blockIdx.y;
    const int bb = bh >> 4, hh = bh & 15;
    const int vlen = valid_lens[bb];
    const int nkb  = (vlen + 63) >> 6;

    const size_t hb = (size_t)bh * NS * NDH;
    const __nv_bfloat16 *Qhi = g_Qhi + hb, *Qlo = g_Qlo + hb;
    const __nv_bfloat16 *Khi = g_Khi + hb, *Klo = g_Klo + hb;
    const __nv_bfloat16 *Vhi = g_Vhi + hb, *Vlo = g_Vlo + hb;

    const int r = lane >> 2, c2 = (lane & 3) * 2;

    uint32_t qh[4][4], ql[4][4];
    {
        const int q0 = qb * 128 + wid * 16;
        #pragma unroll
        for (int t = 0; t < 4; t++) {
            int k0 = t * 16;
            qh[t][0] = *(const uint32_t*)(Qhi + (size_t)(q0 + r    ) * NDH + k0 + c2);
            qh[t][1] = *(const uint32_t*)(Qhi + (size_t)(q0 + r + 8) * NDH + k0 + c2);
            qh[t][2] = *(const uint32_t*)(Qhi + (size_t)(q0 + r    ) * NDH + k0 + c2 + 8);
            qh[t][3] = *(const uint32_t*)(Qhi + (size_t)(q0 + r + 8) * NDH + k0 + c2 + 8);
            ql[t][0] = *(const uint32_t*)(Qlo + (size_t)(q0 + r    ) * NDH + k0 + c2);
            ql[t][1] = *(const uint32_t*)(Qlo + (size_t)(q0 + r + 8) * NDH + k0 + c2);
            ql[t][2] = *(const uint32_t*)(Qlo + (size_t)(q0 + r    ) * NDH + k0 + c2 + 8);
            ql[t][3] = *(const uint32_t*)(Qlo + (size_t)(q0 + r + 8) * NDH + k0 + c2 + 8);
        }
    }

    float m_i[2] = {-1e30f, -1e30f}, l_i[2] = {0.f, 0.f};
    float o[8][4];
    #pragma unroll
    for (int i = 0; i < 8; i++)
        #pragma unroll
        for (int j = 0; j < 4; j++) o[i][j] = 0.f;

    auto cpKV = [&](int kb, int buf) {
        #pragma unroll
        for (int l = 0; l < 8; l++) {
            int f   = tid + l * 256;
            int arr = f >> 9;
            int rr  = (f >> 3) & 63;
            int cc  = f & 7;
            const __nv_bfloat16* srcb =
                (arr == 0) ? Khi : (arr == 1) ? Klo : (arr == 2) ? Vhi : Vlo;
            const void* src = srcb + (size_t)(kb * 64 + rr) * NDH + cc * 8;
            uint32_t dst = sb + buf * ATT_BUF + arr * 8192
                         + rr * 128 + ((cc * 16) ^ ((rr & 7) * 16));
            cpasync16(dst, src);
        }
        CP_COMMIT();
    };

    cpKV(0, 0);

    for (int kb = 0; kb < nkb; kb++) {
        const int buf = kb & 1;
        CP_WAIT0();
        __syncthreads();
        if (kb + 1 < nkb) cpKV(kb + 1, buf ^ 1);

        const uint32_t kHi = sb + buf * ATT_BUF;
        const uint32_t kLo = kHi + 8192;
        const uint32_t vHi = kHi + 16384;
        const uint32_t vLo = kHi + 24576;

        // ---- S = Q K^T (3-pass split, pass-major) ----
        float s[8][4];
        #pragma unroll
        for (int i = 0; i < 8; i++)
            #pragma unroll
            for (int j = 0; j < 4; j++) s[i][j] = 0.f;

        #pragma unroll
        for (int t = 0; t < 4; t++) {
            uint32_t kh[8][2], kl[8][2];
            #pragma unroll
            for (int p = 0; p < 4; p++) {
                int n = p * 16 + (lane & 7) + ((lane >> 4) << 3);
                uint32_t off = n * 128 + ((t * 32 + ((lane >> 3) & 1) * 16) ^ ((n & 7) * 16));
                LDSM_X4(kh[p*2][0], kh[p*2][1], kh[p*2+1][0], kh[p*2+1][1], kHi + off);
                LDSM_X4(kl[p*2][0], kl[p*2][1], kl[p*2+1][0], kl[p*2+1][1], kLo + off);
            }
            #pragma unroll
            for (int nt = 0; nt < 8; nt++)
                MMA_BF16(s[nt], qh[t], kh[nt]);
            #pragma unroll
            for (int nt = 0; nt < 8; nt++)
                MMA_BF16(s[nt], ql[t], kh[nt]);
            #pragma unroll
            for (int nt = 0; nt < 8; nt++)
                MMA_BF16(s[nt], qh[t], kl[nt]);
        }

        // ---- mask tail columns ----
        if (kb == nkb - 1) {
            int cb = kb * 64 + c2;
            #pragma unroll
            for (int nt = 0; nt < 8; nt++) {
                int c0g = cb + nt * 8;
                if (c0g     >= vlen) { s[nt][0] = -1e30f; s[nt][2] = -1e30f; }
                if (c0g + 1 >= vlen) { s[nt][1] = -1e30f; s[nt][3] = -1e30f; }
            }
        }

        // ---- online softmax ----
        float mx0 = -1e30f, mx1 = -1e30f;
        #pragma unroll
        for (int nt = 0; nt < 8; nt++) {
            mx0 = fmaxf(mx0, fmaxf(s[nt][0], s[nt][1]));
            mx1 = fmaxf(mx1, fmaxf(s[nt][2], s[nt][3]));
        }
        mx0 = fmaxf(mx0, __shfl_xor_sync(0xffffffffu, mx0, 1));
        mx0 = fmaxf(mx0, __shfl_xor_sync(0xffffffffu, mx0, 2));
        mx1 = fmaxf(mx1, __shfl_xor_sync(0xffffffffu, mx1, 1));
        mx1 = fmaxf(mx1, __shfl_xor_sync(0xffffffffu, mx1, 2));

        float mn0 = fmaxf(m_i[0], mx0), mn1 = fmaxf(m_i[1], mx1);
        float a0 = __expf(m_i[0] - mn0), a1 = __expf(m_i[1] - mn1);
        m_i[0] = mn0; m_i[1] = mn1;

        float sum0 = 0.f, sum1 = 0.f;
        #pragma unroll
        for (int nt = 0; nt < 8; nt++) {
            s[nt][0] = __expf(s[nt][0] - mn0); sum0 += s[nt][0];
            s[nt][1] = __expf(s[nt][1] - mn0); sum0 += s[nt][1];
            s[nt][2] = __expf(s[nt][2] - mn1); sum1 += s[nt][2];
            s[nt][3] = __expf(s[nt][3] - mn1); sum1 += s[nt][3];
        }
        sum0 += __shfl_xor_sync(0xffffffffu, sum0, 1);
        sum0 += __shfl_xor_sync(0xffffffffu, sum0, 2);
        sum1 += __shfl_xor_sync(0xffffffffu, sum1, 1);
        sum1 += __shfl_xor_sync(0xffffffffu, sum1, 2);
        l_i[0] = l_i[0] * a0 + sum0;
        l_i[1] = l_i[1] * a1 + sum1;
        #pragma unroll
        for (int nt = 0; nt < 8; nt++) {
            o[nt][0] *= a0; o[nt][1] *= a0;
            o[nt][2] *= a1; o[nt][3] *= a1;
        }

        // ---- O += P V (3-pass split, pass-major) ----
        #pragma unroll
        for (int t = 0; t < 4; t++) {
            uint32_t ph[4], pl[4];
            split2(s[2*t  ][0], s[2*t  ][1], ph[0], pl[0]);
            split2(s[2*t  ][2], s[2*t  ][3], ph[1], pl[1]);
            split2(s[2*t+1][0], s[2*t+1][1], ph[2], pl[2]);
            split2(s[2*t+1][2], s[2*t+1][3], ph[3], pl[3]);

            uint32_t vh[8][2], vl[8][2];
            #pragma unroll
            for (int p = 0; p < 4; p++) {
                int rowb = t * 16 + (lane & 15);
                uint32_t off = rowb * 128 + ((p * 32 + (lane >> 4) * 16) ^ ((rowb & 7) * 16));
                LDSM_X4_T(vh[p*2][0], vh[p*2][1], vh[p*2+1][0], vh[p*2+1][1], vHi + off);
                LDSM_X4_T(vl[p*2][0], vl[p*2][1], vl[p*2+1][0], vl[p*2+1][1], vLo + off);
            }
            #pragma unroll
            for (int nt = 0; nt < 8; nt++)
                MMA_BF16(o[nt], ph, vh[nt]);
            #pragma unroll
            for (int nt = 0; nt < 8; nt++)
                MMA_BF16(o[nt], pl, vh[nt]);
            #pragma unroll
            for (int nt = 0; nt < 8; nt++)
                MMA_BF16(o[nt], ph, vl[nt]);
        }
    }

    // ---- epilogue: write [B,S,D] fp32 ----
    const float inv0 = 1.f / l_i[0], inv1 = 1.f / l_i[1];
    const int row0 = qb * 128 + wid * 16 + r;
    float* out0 = g_AO + (size_t)(bb * NS + row0    ) * ND + hh * 64;
    float* out1 = g_AO + (size_t)(bb * NS + row0 + 8) * ND + hh * 64;
    #pragma unroll
    for (int nt = 0; nt < 8; nt++) {
        *(float2*)(out0 + nt * 8 + c2) = make_float2(o[nt][0] * inv0, o[nt][1] * inv0);
        *(float2*)(out1 + nt * 8 + c2) = make_float2(o[nt][2] * inv1, o[nt][3] * inv1);
    }
}

// ---------------------------------------------------------------------------
extern "C" void kernel_launch(void* const* d_in, const int* in_sizes, int n_in,
                              void* d_out, int out_size)
{
    const float* q  = (const float*)d_in[0];
    const float* k  = (const float*)d_in[1];
    const float* v  = (const float*)d_in[2];
    const int*   vl = (const int*)  d_in[3];
    const float* Wq = (const float*)d_in[4];
    const float* Wk = (const float*)d_in[5];
    const float* Wv = (const float*)d_in[6];
    const float* Wo = (const float*)d_in[7];
    float* out = (float*)d_out;

    cudaFuncSetAttribute(gemm_mma_kernel, cudaFuncAttributeMaxDynamicSharedMemorySize,
                         GEMM_SMEM);
    cudaFuncSetAttribute(attn_mma_kernel, cudaFuncAttributeMaxDynamicSharedMemorySize,
                         ATT_SMEM);

    // 1) W transpose + split
    wsplit_kernel<<<dim3(32, 32, 4), 256>>>(Wq, Wk, Wv, Wo);

    // 2) Q/K/V projections -> split bf16 head-major (Q pre-scaled)
    gemm_mma_kernel<<<dim3(ND / 128, (NB * NS) / 128, 3), 256, GEMM_SMEM>>>(
        q, k, v, out, 0);

    // 3) flash attention on HMMA, writes [B,S,D] fp32
    attn_mma_kernel<<<dim3(NS / 128, NB * NH), 256, ATT_SMEM>>>(vl);

    // 4) output projection
    gemm_mma_kernel<<<dim3(ND / 128, (NB * NS) / 128, 1), 256, GEMM_SMEM>>>(
        q, q, q, out, 1);
}

// round 6
// speedup vs baseline: 2.9890x; 1.1022x over previous
#include <cuda_runtime.h>
#include <cuda_bf16.h>
#include <stdint.h>

#define NB  2
#define NS  2048
#define ND  1024
#define NH  16
#define NDH 64

// Scratch (allocation-free rule: __device__ globals).
__device__ __nv_bfloat16 g_Whi[4u << 20];     // 4 x W^T hi: [n][k] k-major
__device__ __nv_bfloat16 g_Wlo[4u << 20];     // 4 x W^T lo
__device__ __nv_bfloat16 g_Xhi[3u << 22], g_Xlo[3u << 22];   // split Xq/Xk/Xv [4096][1024]
__device__ __nv_bfloat16 g_AOhi[1u << 22], g_AOlo[1u << 22]; // split attn out [4096][1024]
// Q/K/V split bf16, head-major [B,H,S,DH]
__device__ __nv_bfloat16 g_Qhi[NB*NH*NS*NDH], g_Qlo[NB*NH*NS*NDH];
__device__ __nv_bfloat16 g_Khi[NB*NH*NS*NDH], g_Klo[NB*NH*NS*NDH];
__device__ __nv_bfloat16 g_Vhi[NB*NH*NS*NDH], g_Vlo[NB*NH*NS*NDH];

// ---------------------------------------------------------------------------
// helpers
// ---------------------------------------------------------------------------
__device__ __forceinline__ uint32_t smem_u32(const void* p) {
    uint32_t a;
    asm("{ .reg .u64 t; cvta.to.shared.u64 t, %1; cvt.u32.u64 %0, t; }" : "=r"(a) : "l"(p));
    return a;
}
__device__ __forceinline__ void cpasync16(uint32_t dst, const void* src) {
    asm volatile("cp.async.cg.shared.global [%0], [%1], 16;" :: "r"(dst), "l"(src));
}
#define CP_COMMIT() asm volatile("cp.async.commit_group;" ::: "memory")
#define CP_WAIT0()  asm volatile("cp.async.wait_group 0;" ::: "memory")
#define CP_WAIT1()  asm volatile("cp.async.wait_group 1;" ::: "memory")

#define LDSM_X4(r0, r1, r2, r3, addr)                                          \
    asm volatile("ldmatrix.sync.aligned.m8n8.x4.shared.b16 {%0,%1,%2,%3}, [%4];" \
        : "=r"(r0), "=r"(r1), "=r"(r2), "=r"(r3) : "r"(addr))
#define LDSM_X4_T(r0, r1, r2, r3, addr)                                        \
    asm volatile("ldmatrix.sync.aligned.m8n8.x4.trans.shared.b16 {%0,%1,%2,%3}, [%4];" \
        : "=r"(r0), "=r"(r1), "=r"(r2), "=r"(r3) : "r"(addr))

#define MMA_BF16(d, a, b)                                                      \
    asm volatile("mma.sync.aligned.m16n8k16.row.col.f32.bf16.bf16.f32 "        \
        "{%0,%1,%2,%3},{%4,%5,%6,%7},{%8,%9},{%0,%1,%2,%3};"                   \
        : "+f"((d)[0]), "+f"((d)[1]), "+f"((d)[2]), "+f"((d)[3])               \
        : "r"((a)[0]), "r"((a)[1]), "r"((a)[2]), "r"((a)[3]),                  \
          "r"((b)[0]), "r"((b)[1]))

__device__ __forceinline__ void split2(float a, float b, uint32_t& hi, uint32_t& lo) {
    __nv_bfloat16 ha = __float2bfloat16(a), hb = __float2bfloat16(b);
    float ra = a - __bfloat162float(ha), rb = b - __bfloat162float(hb);
    hi = (uint32_t)__bfloat16_as_ushort(ha) | ((uint32_t)__bfloat16_as_ushort(hb) << 16);
    __nv_bfloat16 la = __float2bfloat16(ra), lb = __float2bfloat16(rb);
    lo = (uint32_t)__bfloat16_as_ushort(la) | ((uint32_t)__bfloat16_as_ushort(lb) << 16);
}

// ---------------------------------------------------------------------------
// X split: fp32 -> bf16 hi/lo, row-major passthrough. One float4 per thread.
// ---------------------------------------------------------------------------
__global__ __launch_bounds__(256) void splitx_kernel(
    const float* __restrict__ X0, const float* __restrict__ X1,
    const float* __restrict__ X2)
{
    const int z = blockIdx.y;
    const float* X = (z == 0) ? X0 : (z == 1) ? X1 : X2;
    __nv_bfloat16* Ohi = g_Xhi + ((size_t)z << 22);
    __nv_bfloat16* Olo = g_Xlo + ((size_t)z << 22);
    size_t idx = (size_t)blockIdx.x * 256 + threadIdx.x;   // float4 index
    float4 v = *((const float4*)X + idx);
    uint2 hi, lo;
    split2(v.x, v.y, hi.x, lo.x);
    split2(v.z, v.w, hi.y, lo.y);
    *((uint2*)Ohi + idx) = hi;
    *((uint2*)Olo + idx) = lo;
}

// ---------------------------------------------------------------------------
// W transpose + fp32 -> (bf16 hi, bf16 lo). Out[n][k] = W[k][n].
// ---------------------------------------------------------------------------
__global__ __launch_bounds__(256) void wsplit_kernel(
    const float* __restrict__ W0, const float* __restrict__ W1,
    const float* __restrict__ W2, const float* __restrict__ W3)
{
    __shared__ float t[32][33];
    const float* W = (blockIdx.z == 0) ? W0 : (blockIdx.z == 1) ? W1 :
                     (blockIdx.z == 2) ? W2 : W3;
    __nv_bfloat16* Ohi = g_Whi + ((size_t)blockIdx.z << 20);
    __nv_bfloat16* Olo = g_Wlo + ((size_t)blockIdx.z << 20);

    int tx = threadIdx.x & 31, ty = threadIdx.x >> 5;
    int n0 = blockIdx.x * 32, k0 = blockIdx.y * 32;

    #pragma unroll
    for (int i = 0; i < 4; i++)
        t[ty + i*8][tx] = W[(size_t)(k0 + ty + i*8) * ND + n0 + tx];
    __syncthreads();
    #pragma unroll
    for (int i = 0; i < 4; i++) {
        float v = t[tx][ty + i*8];
        __nv_bfloat16 h = __float2bfloat16(v);
        __nv_bfloat16 l = __float2bfloat16(v - __bfloat162float(h));
        size_t idx = (size_t)(n0 + ty + i*8) * ND + k0 + tx;
        Ohi[idx] = h; Olo[idx] = l;
    }
}

// ---------------------------------------------------------------------------
// HMMA split-bf16 GEMM, all-cp.async: C = A @ W^T-stored-B.
// CTA 256M x 128N, BK=64, 512 threads = 16 warps (8m x 2n), warp tile 32x64.
// Double-buffered 2 x 96KB. 3 passes: Ah*Bh + Ah*Bl + Al*Bh.
// ---------------------------------------------------------------------------
#define GBUF   98304
#define G_AHI  0
#define G_ALO  32768
#define G_BHI  65536
#define G_BLO  81920
#define GEMM_SMEM (2 * GBUF)   // 192 KB

__global__ __launch_bounds__(512, 1) void gemm_mma_kernel(float* __restrict__ Cout, int mode)
{
    extern __shared__ char smc[];
    const uint32_t sb = smem_u32(smc);
    const int tid  = threadIdx.x;
    const int wid  = tid >> 5, lane = tid & 31;
    const int z    = blockIdx.z;

    const __nv_bfloat16 *Ahi_g, *Alo_g, *Whi, *Wlo;
    __nv_bfloat16 *Ohi = 0, *Olo = 0;
    float osc = 1.f;
    if (mode == 0) {
        Ahi_g = g_Xhi + ((size_t)z << 22);
        Alo_g = g_Xlo + ((size_t)z << 22);
        Whi = g_Whi + ((size_t)z << 20);
        Wlo = g_Wlo + ((size_t)z << 20);
        Ohi = (z == 0) ? g_Qhi : (z == 1) ? g_Khi : g_Vhi;
        Olo = (z == 0) ? g_Qlo : (z == 1) ? g_Klo : g_Vlo;
        if (z == 0) osc = 0.125f;
    } else {
        Ahi_g = g_AOhi; Alo_g = g_AOlo;
        Whi = g_Whi + ((size_t)3 << 20);
        Wlo = g_Wlo + ((size_t)3 << 20);
    }
    const int bM = blockIdx.y * 256, bN = blockIdx.x * 128;
    const int warp_m = (wid & 7) * 32, warp_n = (wid >> 3) * 64;

    float acc[16][4];
    #pragma unroll
    for (int i = 0; i < 16; i++)
        #pragma unroll
        for (int j = 0; j < 4; j++) acc[i][j] = 0.f;

    auto cpStage = [&](int s, int buf) {
        uint32_t base = sb + buf * GBUF;
        #pragma unroll
        for (int l = 0; l < 12; l++) {
            int f = tid + l * 512;
            const __nv_bfloat16* src;
            uint32_t dst;
            if (f < 4096) {                     // A hi/lo: 256 rows x 8 chunks
                int arr = f >> 11;
                int r = (f >> 3) & 255, c = f & 7;
                src = (arr ? Alo_g : Ahi_g) + (size_t)(bM + r) * ND + s * 64 + c * 8;
                dst = base + (arr ? G_ALO : G_AHI) + r * 128 + ((c * 16) ^ ((r & 7) * 16));
            } else {                            // B hi/lo: 128 rows x 8 chunks
                int g = f - 4096;
                int arr = g >> 10;
                int r = (g >> 3) & 127, c = g & 7;
                src = (arr ? Wlo : Whi) + (size_t)(bN + r) * ND + s * 64 + c * 8;
                dst = base + (arr ? G_BLO : G_BHI) + r * 128 + ((c * 16) ^ ((r & 7) * 16));
            }
            cpasync16(dst, src);
        }
        CP_COMMIT();
    };

    cpStage(0, 0);

    for (int s = 0; s < 16; s++) {
        const int buf = s & 1;
        if (s + 1 < 16) { cpStage(s + 1, buf ^ 1); CP_WAIT1(); }
        else            { CP_WAIT0(); }
        __syncthreads();

        const uint32_t aHi = sb + buf * GBUF + G_AHI;
        const uint32_t aLo = sb + buf * GBUF + G_ALO;
        const uint32_t bHi = sb + buf * GBUF + G_BHI;
        const uint32_t bLo = sb + buf * GBUF + G_BLO;

        #pragma unroll
        for (int kk = 0; kk < 4; kk++) {
            const int k0 = kk * 16;
            uint32_t ah[2][4], al[2][4];
            #pragma unroll
            for (int mt = 0; mt < 2; mt++) {
                int row = warp_m + mt * 16 + (lane & 15);
                uint32_t off = row * 128 + ((k0 * 2 + (lane >> 4) * 16) ^ ((row & 7) * 16));
                LDSM_X4(ah[mt][0], ah[mt][1], ah[mt][2], ah[mt][3], aHi + off);
                LDSM_X4(al[mt][0], al[mt][1], al[mt][2], al[mt][3], aLo + off);
            }
            #pragma unroll
            for (int h = 0; h < 2; h++) {       // two 32-col halves of the warp's 64n
                uint32_t bh[4][2], bl[4][2];
                #pragma unroll
                for (int p = 0; p < 2; p++) {
                    int n = warp_n + h * 32 + p * 16 + (lane & 7) + ((lane >> 4) << 3);
                    uint32_t off = n * 128 + ((k0 * 2 + ((lane >> 3) & 1) * 16) ^ ((n & 7) * 16));
                    LDSM_X4(bh[p*2][0], bh[p*2][1], bh[p*2+1][0], bh[p*2+1][1], bHi + off);
                    LDSM_X4(bl[p*2][0], bl[p*2][1], bl[p*2+1][0], bl[p*2+1][1], bLo + off);
                }
                #pragma unroll
                for (int mt = 0; mt < 2; mt++)
                    #pragma unroll
                    for (int nt = 0; nt < 4; nt++)
                        MMA_BF16(acc[mt*8 + h*4 + nt], ah[mt], bh[nt]);
                #pragma unroll
                for (int mt = 0; mt < 2; mt++)
                    #pragma unroll
                    for (int nt = 0; nt < 4; nt++)
                        MMA_BF16(acc[mt*8 + h*4 + nt], ah[mt], bl[nt]);
                #pragma unroll
                for (int mt = 0; mt < 2; mt++)
                    #pragma unroll
                    for (int nt = 0; nt < 4; nt++)
                        MMA_BF16(acc[mt*8 + h*4 + nt], al[mt], bh[nt]);
            }
        }
        __syncthreads();
    }

    #pragma unroll
    for (int mt = 0; mt < 2; mt++)
        #pragma unroll
        for (int nt = 0; nt < 8; nt++) {
            int m0 = bM + warp_m + mt * 16 + (lane >> 2);
            int n  = bN + warp_n + nt * 8 + (lane & 3) * 2;
            float* a4 = acc[mt*8+nt];
            if (mode == 0) {
                int h = n >> 6, dh = n & 63;
                int b0 = m0 >> 11, s0 = m0 & 2047;
                int m1 = m0 + 8, b1 = m1 >> 11, s1 = m1 & 2047;
                size_t i0 = ((size_t)(b0 * NH + h) * NS + s0) * NDH + dh;
                size_t i1 = ((size_t)(b1 * NH + h) * NS + s1) * NDH + dh;
                uint32_t h0, l0, h1, l1;
                split2(a4[0] * osc, a4[1] * osc, h0, l0);
                split2(a4[2] * osc, a4[3] * osc, h1, l1);
                *(uint32_t*)(Ohi + i0) = h0; *(uint32_t*)(Olo + i0) = l0;
                *(uint32_t*)(Ohi + i1) = h1; *(uint32_t*)(Olo + i1) = l1;
            } else {
                *(float2*)(Cout + (size_t)m0 * ND + n)       = make_float2(a4[0], a4[1]);
                *(float2*)(Cout + (size_t)(m0 + 8) * ND + n) = make_float2(a4[2], a4[3]);
            }
        }
}

// ---------------------------------------------------------------------------
// Flash attention on HMMA, split-bf16, 3-pass, pass-major.
// CTA = 128 q x 64 k, 8 warps, double-buffered K/V hi/lo.
// Epilogue writes split bf16 to g_AOhi/g_AOlo ([B*S][D] row-major).
// ---------------------------------------------------------------------------
#define ATT_BUF  32768
#define ATT_SMEM (2 * ATT_BUF)

__global__ __launch_bounds__(256, 1) void attn_mma_kernel(const int* __restrict__ valid_lens)
{
    extern __shared__ char smc[];
    const uint32_t sb = smem_u32(smc);
    const int tid = threadIdx.x, wid = tid >> 5, lane = tid & 31;
    const int qb = blockIdx.x, bh = blockIdx.y;
    const int bb = bh >> 4, head = bh & 15;
    const int vlen = valid_lens[bb];
    const int nkb  = (vlen + 63) >> 6;

    const size_t hbase = (size_t)bh * NS * NDH;
    const __nv_bfloat16 *Qhi = g_Qhi + hbase, *Qlo = g_Qlo + hbase;
    const __nv_bfloat16 *Khi = g_Khi + hbase, *Klo = g_Klo + hbase;
    const __nv_bfloat16 *Vhi = g_Vhi + hbase, *Vlo = g_Vlo + hbase;

    const int r = lane >> 2, c2 = (lane & 3) * 2;

    uint32_t qh[4][4], ql[4][4];
    {
        const int q0 = qb * 128 + wid * 16;
        #pragma unroll
        for (int t = 0; t < 4; t++) {
            int k0 = t * 16;
            qh[t][0] = *(const uint32_t*)(Qhi + (size_t)(q0 + r    ) * NDH + k0 + c2);
            qh[t][1] = *(const uint32_t*)(Qhi + (size_t)(q0 + r + 8) * NDH + k0 + c2);
            qh[t][2] = *(const uint32_t*)(Qhi + (size_t)(q0 + r    ) * NDH + k0 + c2 + 8);
            qh[t][3] = *(const uint32_t*)(Qhi + (size_t)(q0 + r + 8) * NDH + k0 + c2 + 8);
            ql[t][0] = *(const uint32_t*)(Qlo + (size_t)(q0 + r    ) * NDH + k0 + c2);
            ql[t][1] = *(const uint32_t*)(Qlo + (size_t)(q0 + r + 8) * NDH + k0 + c2);
            ql[t][2] = *(const uint32_t*)(Qlo + (size_t)(q0 + r    ) * NDH + k0 + c2 + 8);
            ql[t][3] = *(const uint32_t*)(Qlo + (size_t)(q0 + r + 8) * NDH + k0 + c2 + 8);
        }
    }

    float m_i[2] = {-1e30f, -1e30f}, l_i[2] = {0.f, 0.f};
    float o[8][4];
    #pragma unroll
    for (int i = 0; i < 8; i++)
        #pragma unroll
        for (int j = 0; j < 4; j++) o[i][j] = 0.f;

    auto cpKV = [&](int kb, int buf) {
        #pragma unroll
        for (int l = 0; l < 8; l++) {
            int f   = tid + l * 256;
            int arr = f >> 9;
            int rr  = (f >> 3) & 63;
            int cc  = f & 7;
            const __nv_bfloat16* srcb =
                (arr == 0) ? Khi : (arr == 1) ? Klo : (arr == 2) ? Vhi : Vlo;
            const void* src = srcb + (size_t)(kb * 64 + rr) * NDH + cc * 8;
            uint32_t dst = sb + buf * ATT_BUF + arr * 8192
                         + rr * 128 + ((cc * 16) ^ ((rr & 7) * 16));
            cpasync16(dst, src);
        }
        CP_COMMIT();
    };

    cpKV(0, 0);

    for (int kb = 0; kb < nkb; kb++) {
        const int buf = kb & 1;
        CP_WAIT0();
        __syncthreads();
        if (kb + 1 < nkb) cpKV(kb + 1, buf ^ 1);

        const uint32_t kHi = sb + buf * ATT_BUF;
        const uint32_t kLo = kHi + 8192;
        const uint32_t vHi = kHi + 16384;
        const uint32_t vLo = kHi + 24576;

        float s[8][4];
        #pragma unroll
        for (int i = 0; i < 8; i++)
            #pragma unroll
            for (int j = 0; j < 4; j++) s[i][j] = 0.f;

        #pragma unroll
        for (int t = 0; t < 4; t++) {
            uint32_t kh[8][2], kl[8][2];
            #pragma unroll
            for (int p = 0; p < 4; p++) {
                int n = p * 16 + (lane & 7) + ((lane >> 4) << 3);
                uint32_t off = n * 128 + ((t * 32 + ((lane >> 3) & 1) * 16) ^ ((n & 7) * 16));
                LDSM_X4(kh[p*2][0], kh[p*2][1], kh[p*2+1][0], kh[p*2+1][1], kHi + off);
                LDSM_X4(kl[p*2][0], kl[p*2][1], kl[p*2+1][0], kl[p*2+1][1], kLo + off);
            }
            #pragma unroll
            for (int nt = 0; nt < 8; nt++)
                MMA_BF16(s[nt], qh[t], kh[nt]);
            #pragma unroll
            for (int nt = 0; nt < 8; nt++)
                MMA_BF16(s[nt], ql[t], kh[nt]);
            #pragma unroll
            for (int nt = 0; nt < 8; nt++)
                MMA_BF16(s[nt], qh[t], kl[nt]);
        }

        if (kb == nkb - 1) {
            int cb = kb * 64 + c2;
            #pragma unroll
            for (int nt = 0; nt < 8; nt++) {
                int c0g = cb + nt * 8;
                if (c0g     >= vlen) { s[nt][0] = -1e30f; s[nt][2] = -1e30f; }
                if (c0g + 1 >= vlen) { s[nt][1] = -1e30f; s[nt][3] = -1e30f; }
            }
        }

        float mx0 = -1e30f, mx1 = -1e30f;
        #pragma unroll
        for (int nt = 0; nt < 8; nt++) {
            mx0 = fmaxf(mx0, fmaxf(s[nt][0], s[nt][1]));
            mx1 = fmaxf(mx1, fmaxf(s[nt][2], s[nt][3]));
        }
        mx0 = fmaxf(mx0, __shfl_xor_sync(0xffffffffu, mx0, 1));
        mx0 = fmaxf(mx0, __shfl_xor_sync(0xffffffffu, mx0, 2));
        mx1 = fmaxf(mx1, __shfl_xor_sync(0xffffffffu, mx1, 1));
        mx1 = fmaxf(mx1, __shfl_xor_sync(0xffffffffu, mx1, 2));

        float mn0 = fmaxf(m_i[0], mx0), mn1 = fmaxf(m_i[1], mx1);
        float a0 = __expf(m_i[0] - mn0), a1 = __expf(m_i[1] - mn1);
        m_i[0] = mn0; m_i[1] = mn1;

        float sum0 = 0.f, sum1 = 0.f;
        #pragma unroll
        for (int nt = 0; nt < 8; nt++) {
            s[nt][0] = __expf(s[nt][0] - mn0); sum0 += s[nt][0];
            s[nt][1] = __expf(s[nt][1] - mn0); sum0 += s[nt][1];
            s[nt][2] = __expf(s[nt][2] - mn1); sum1 += s[nt][2];
            s[nt][3] = __expf(s[nt][3] - mn1); sum1 += s[nt][3];
        }
        sum0 += __shfl_xor_sync(0xffffffffu, sum0, 1);
        sum0 += __shfl_xor_sync(0xffffffffu, sum0, 2);
        sum1 += __shfl_xor_sync(0xffffffffu, sum1, 1);
        sum1 += __shfl_xor_sync(0xffffffffu, sum1, 2);
        l_i[0] = l_i[0] * a0 + sum0;
        l_i[1] = l_i[1] * a1 + sum1;
        #pragma unroll
        for (int nt = 0; nt < 8; nt++) {
            o[nt][0] *= a0; o[nt][1] *= a0;
            o[nt][2] *= a1; o[nt][3] *= a1;
        }

        #pragma unroll
        for (int t = 0; t < 4; t++) {
            uint32_t ph[4], pl[4];
            split2(s[2*t  ][0], s[2*t  ][1], ph[0], pl[0]);
            split2(s[2*t  ][2], s[2*t  ][3], ph[1], pl[1]);
            split2(s[2*t+1][0], s[2*t+1][1], ph[2], pl[2]);
            split2(s[2*t+1][2], s[2*t+1][3], ph[3], pl[3]);

            uint32_t vh[8][2], vl[8][2];
            #pragma unroll
            for (int p = 0; p < 4; p++) {
                int rowb = t * 16 + (lane & 15);
                uint32_t off = rowb * 128 + ((p * 32 + (lane >> 4) * 16) ^ ((rowb & 7) * 16));
                LDSM_X4_T(vh[p*2][0], vh[p*2][1], vh[p*2+1][0], vh[p*2+1][1], vHi + off);
                LDSM_X4_T(vl[p*2][0], vl[p*2][1], vl[p*2+1][0], vl[p*2+1][1], vLo + off);
            }
            #pragma unroll
            for (int nt = 0; nt < 8; nt++)
                MMA_BF16(o[nt], ph, vh[nt]);
            #pragma unroll
            for (int nt = 0; nt < 8; nt++)
                MMA_BF16(o[nt], pl, vh[nt]);
            #pragma unroll
            for (int nt = 0; nt < 8; nt++)
                MMA_BF16(o[nt], ph, vl[nt]);
        }
    }

    // epilogue: write split bf16 [B*S][D]
    const float inv0 = 1.f / l_i[0], inv1 = 1.f / l_i[1];
    const int row0 = qb * 128 + wid * 16 + r;
    const size_t base0 = (size_t)(bb * NS + row0    ) * ND + head * 64;
    const size_t base1 = (size_t)(bb * NS + row0 + 8) * ND + head * 64;
    #pragma unroll
    for (int nt = 0; nt < 8; nt++) {
        uint32_t h0, l0, h1, l1;
        split2(o[nt][0] * inv0, o[nt][1] * inv0, h0, l0);
        split2(o[nt][2] * inv1, o[nt][3] * inv1, h1, l1);
        *(uint32_t*)(g_AOhi + base0 + nt * 8 + c2) = h0;
        *(uint32_t*)(g_AOlo + base0 + nt * 8 + c2) = l0;
        *(uint32_t*)(g_AOhi + base1 + nt * 8 + c2) = h1;
        *(uint32_t*)(g_AOlo + base1 + nt * 8 + c2) = l1;
    }
}

// ---------------------------------------------------------------------------
extern "C" void kernel_launch(void* const* d_in, const int* in_sizes, int n_in,
                              void* d_out, int out_size)
{
    const float* q  = (const float*)d_in[0];
    const float* k  = (const float*)d_in[1];
    const float* v  = (const float*)d_in[2];
    const int*   vl = (const int*)  d_in[3];
    const float* Wq = (const float*)d_in[4];
    const float* Wk = (const float*)d_in[5];
    const float* Wv = (const float*)d_in[6];
    const float* Wo = (const float*)d_in[7];
    float* out = (float*)d_out;

    cudaFuncSetAttribute(gemm_mma_kernel, cudaFuncAttributeMaxDynamicSharedMemorySize,
                         GEMM_SMEM);
    cudaFuncSetAttribute(attn_mma_kernel, cudaFuncAttributeMaxDynamicSharedMemorySize,
                         ATT_SMEM);

    // 1) input splits (X and W)
    splitx_kernel<<<dim3(4096, 3), 256>>>(q, k, v);
    wsplit_kernel<<<dim3(32, 32, 4), 256>>>(Wq, Wk, Wv, Wo);

    // 2) Q/K/V projections -> split bf16 head-major (Q pre-scaled)
    gemm_mma_kernel<<<dim3(ND / 128, (NB * NS) / 256, 3), 512, GEMM_SMEM>>>(out, 0);

    // 3) flash attention on HMMA, writes split bf16 [B,S,D]
    attn_mma_kernel<<<dim3(NS / 128, NB * NH), 256, ATT_SMEM>>>(vl);

    // 4) output projection -> fp32 d_out
    gemm_mma_kernel<<<dim3(ND / 128, (NB * NS) / 256, 1), 512, GEMM_SMEM>>>(out, 1);
}